// round 5
// baseline (speedup 1.0000x reference)
#include <cuda_runtime.h>
#include <cstdint>

// ---------------- problem dims ----------------
#define BB 128
#define TT 256
#define ND 128
#define KD 128
#define VD 128
#define FD 2048
#define OD 4096   // ODIM*NDIM
#define SQ 384    // fused qkv row stride

// ---------------- device scratch (no allocations allowed) ----------------
__device__ float g_qkv[(size_t)BB * TT * SQ];    // fused q|k|v, stride 384
__device__ float g_wqkv[ND * SQ];                // packed [128][384] weight
__device__ float g_bqkv[SQ];
__device__ float g_r[(size_t)BB * TT * VD];
__device__ float g_h1[BB * FD];
__device__ float g_h2[BB * FD];
__device__ float g_part[(size_t)32 * BB * FD];   // split-K partials (max 8.39M floats)

// ---------------- tf32 mma helpers ----------------
__device__ __forceinline__ uint32_t f2tf(float f) {
    uint32_t u;
    asm("cvt.rna.tf32.f32 %0, %1;" : "=r"(u) : "f"(f));
    return u;
}
__device__ __forceinline__ float f2tff(float f) { return __uint_as_float(f2tf(f)); }

__device__ __forceinline__ void mma8(float* c, const uint32_t* a, uint32_t b0, uint32_t b1) {
    asm volatile(
        "mma.sync.aligned.m16n8k8.row.col.f32.tf32.tf32.f32 "
        "{%0,%1,%2,%3},{%4,%5,%6,%7},{%8,%9},{%0,%1,%2,%3};"
        : "+f"(c[0]), "+f"(c[1]), "+f"(c[2]), "+f"(c[3])
        : "r"(a[0]), "r"(a[1]), "r"(a[2]), "r"(a[3]), "r"(b0), "r"(b1));
}

__device__ __forceinline__ void cp16(void* dst, const void* src) {
    uint32_t d = (uint32_t)__cvta_generic_to_shared(dst);
    asm volatile("cp.async.cg.shared.global [%0], [%1], 16;" :: "r"(d), "l"(src));
}
__device__ __forceinline__ void cp_commit() { asm volatile("cp.async.commit_group;"); }
template <int N> __device__ __forceinline__ void cp_wait() {
    asm volatile("cp.async.wait_group %0;" :: "n"(N));
}

// ---------------- pack QKV weights ----------------
__global__ void pack_qkv_kernel(
    const float* __restrict__ Qw, const float* __restrict__ Kw, const float* __restrict__ Vw,
    const float* __restrict__ Qb, const float* __restrict__ Kb, const float* __restrict__ Vb,
    float* __restrict__ w, float* __restrict__ bia)
{
    int idx = blockIdx.x * 256 + threadIdx.x;
    if (idx < ND * SQ) {
        int k = idx / SQ, c = idx % SQ;
        float v;
        if (c < 128)       v = Qw[k * 128 + c];
        else if (c < 256)  v = Kw[k * 128 + c - 128];
        else               v = Vw[k * 128 + c - 256];
        w[idx] = v;
    }
    if (idx < SQ) {
        float v;
        if (idx < 128)      v = Qb[idx];
        else if (idx < 256) v = Kb[idx - 128];
        else                v = Vb[idx - 256];
        bia[idx] = v;
    }
}

// ---------------- pipelined tf32 GEMM ----------------
// C[M,N] = A[M,K] @ B[K,N] row-major fp32. CTA 128x128, 256 threads,
// 8 warps (2m x 4n), warp tile 64x32, kstep 32, 3-stage cp.async.
// grid: x=N/128, y=M/128, z=splits.
// splits==1: fused bias (+sigmoid if act). splits>1: partials at C + z*M*N.
#define ASTRIDE 36
#define BSTRIDE 136
#define NSTAGE 3
#define A_ELEMS (128 * ASTRIDE)
#define B_ELEMS (32 * BSTRIDE)
#define GEMM_SMEM (NSTAGE * (A_ELEMS + B_ELEMS) * 4)

__global__ __launch_bounds__(256, 2) void gemm_tf32_pipe(
    const float* __restrict__ A, const float* __restrict__ Bm,
    float* __restrict__ C, const float* __restrict__ bias,
    int M, int N, int K, int act)
{
    extern __shared__ float smp[];
    float* As = smp;                          // [NSTAGE][128][ASTRIDE]
    float* Bs = smp + NSTAGE * A_ELEMS;       // [NSTAGE][32][BSTRIDE]

    const int splits = gridDim.z;
    const int kchunk = K / splits;
    const int kbeg = blockIdx.z * kchunk;
    const int m0 = blockIdx.y * 128;
    const int n0 = blockIdx.x * 128;
    const int tid = threadIdx.x;
    const int warp = tid >> 5, lane = tid & 31;
    const int wm = warp & 1, wn = warp >> 1;      // 2(M) x 4(N); warp tile 64x32
    const int gi = lane >> 2, tg = lane & 3;

    float acc[4][4][4];
#pragma unroll
    for (int i = 0; i < 4; i++)
#pragma unroll
        for (int j = 0; j < 4; j++)
#pragma unroll
            for (int x = 0; x < 4; x++) acc[i][j][x] = 0.f;

    auto stage = [&](int s, int kb) {
        float* as = As + s * A_ELEMS;
        float* bs = Bs + s * B_ELEMS;
#pragma unroll
        for (int it = 0; it < 4; it++) {           // A: 128x32 floats = 1024 float4
            int flat = it * 256 + tid;
            int row = flat >> 3, c4 = (flat & 7) << 2;
            cp16(&as[row * ASTRIDE + c4], A + (size_t)(m0 + row) * K + kb + c4);
        }
#pragma unroll
        for (int it = 0; it < 4; it++) {           // B: 32x128 floats = 1024 float4
            int flat = it * 256 + tid;
            int row = flat >> 5, c4 = (flat & 31) << 2;
            cp16(&bs[row * BSTRIDE + c4], Bm + (size_t)(kb + row) * N + n0 + c4);
        }
        cp_commit();
    };

    const int nsteps = kchunk / 32;
    stage(0, kbeg);
    if (nsteps > 1) stage(1, kbeg + 32);

    for (int s = 0; s < nsteps; s++) {
        if (s + 1 < nsteps) cp_wait<1>(); else cp_wait<0>();
        __syncthreads();
        // prefetch stage s+2 into the buffer consumed at iter s-1 (safe: barrier above)
        if (s + 2 < nsteps) stage((s + 2) % NSTAGE, kbeg + (s + 2) * 32);

        float* as = As + (s % NSTAGE) * A_ELEMS;
        float* bs = Bs + (s % NSTAGE) * B_ELEMS;
#pragma unroll
        for (int kk = 0; kk < 32; kk += 8) {
            uint32_t a[4][4];
#pragma unroll
            for (int mi = 0; mi < 4; mi++) {
                int r0 = wm * 64 + mi * 16;
                a[mi][0] = f2tf(as[(r0 + gi) * ASTRIDE + kk + tg]);
                a[mi][1] = f2tf(as[(r0 + gi + 8) * ASTRIDE + kk + tg]);
                a[mi][2] = f2tf(as[(r0 + gi) * ASTRIDE + kk + tg + 4]);
                a[mi][3] = f2tf(as[(r0 + gi + 8) * ASTRIDE + kk + tg + 4]);
            }
            uint32_t b[4][2];
#pragma unroll
            for (int ni = 0; ni < 4; ni++) {
                int c0 = wn * 32 + ni * 8;
                b[ni][0] = f2tf(bs[(kk + tg) * BSTRIDE + c0 + gi]);
                b[ni][1] = f2tf(bs[(kk + tg + 4) * BSTRIDE + c0 + gi]);
            }
#pragma unroll
            for (int mi = 0; mi < 4; mi++)
#pragma unroll
                for (int ni = 0; ni < 4; ni++)
                    mma8(acc[mi][ni], a[mi], b[ni][0], b[ni][1]);
        }
    }

    __syncthreads();   // make sure no warp is still reading smem? (no reuse after; cheap)

    const bool fused = (splits == 1);
    float* Cout = C + (size_t)blockIdx.z * (size_t)M * (size_t)N;
#pragma unroll
    for (int mi = 0; mi < 4; mi++) {
#pragma unroll
        for (int ni = 0; ni < 4; ni++) {
            int row = m0 + wm * 64 + mi * 16 + gi;
            int col = n0 + wn * 32 + ni * 8 + tg * 2;
            float c0 = acc[mi][ni][0], c1 = acc[mi][ni][1];
            float c2 = acc[mi][ni][2], c3 = acc[mi][ni][3];
            if (fused) {
                float bv0 = bias ? bias[col] : 0.f;
                float bv1 = bias ? bias[col + 1] : 0.f;
                c0 += bv0; c1 += bv1; c2 += bv0; c3 += bv1;
                if (act == 1) {
                    c0 = 1.f / (1.f + __expf(-c0));
                    c1 = 1.f / (1.f + __expf(-c1));
                    c2 = 1.f / (1.f + __expf(-c2));
                    c3 = 1.f / (1.f + __expf(-c3));
                }
            }
            Cout[(size_t)row * N + col] = c0;
            Cout[(size_t)row * N + col + 1] = c1;
            Cout[(size_t)(row + 8) * N + col] = c2;
            Cout[(size_t)(row + 8) * N + col + 1] = c3;
        }
    }
}

// ---------------- split reduce + bias + activation ----------------
__global__ __launch_bounds__(256) void reduce_kernel(
    const float* __restrict__ part, const float* __restrict__ bias,
    float* __restrict__ out, int MN, int N, int splits, int act)
{
    int i = blockIdx.x * 256 + threadIdx.x;
    if (i >= MN) return;
    float s = 0.f;
    for (int z = 0; z < splits; z++) s += part[(size_t)z * MN + i];
    s += bias[i % N];
    if (act) s = 1.f / (1.f + __expf(-s));
    out[i] = s;
}

// ---------------- attention: softmax(K Q^T) V ----------------
// grid (4, 128): 64-row t-tile, one batch per blockIdx.y. 256 threads.
// All smem operands are pre-rounded to tf32 at staging time -> inner loop is LDS+MMA only.
#define ATTN_SMEM_BYTES ((64 * 132 + 64 * 260 + 128 * 132 + 64) * 4)

__global__ __launch_bounds__(256) void attn_kernel(
    const float* __restrict__ qkv, float* __restrict__ r)
{
    extern __shared__ float sm[];
    float* kt = sm;                    // [64][132]  tf32-rounded k rows
    float* S = sm + 64 * 132;          // [64][260]  scores -> rounded exp
    float* qs = S + 64 * 260;          // [128][132] q chunk (rounded), reused for v
    float* rs = qs + 128 * 132;        // [64]       1/rowsum

    const int b = blockIdx.y;
    const int t0 = blockIdx.x * 64;
    const float* qb = qkv + (size_t)b * TT * SQ;                 // stride SQ
    const float* kb = qkv + ((size_t)b * TT + t0) * SQ + 128;
    const float* vb = qkv + (size_t)b * TT * SQ + 256;
    const int tid = threadIdx.x, warp = tid >> 5, lane = tid & 31;
    const int gi = lane >> 2, tg = lane & 3;
    const int wm = warp & 1, wn = warp >> 1;      // 2(M) x 4(N); warp tile 32x32

    // stage k tile [64][128], rounded
#pragma unroll
    for (int it = 0; it < 8; it++) {
        int idx = tid + it * 256;
        int row = idx >> 5;
        int c4 = (idx & 31) << 2;
        float4 v4 = *reinterpret_cast<const float4*>(kb + (size_t)row * SQ + c4);
        v4.x = f2tff(v4.x); v4.y = f2tff(v4.y); v4.z = f2tff(v4.z); v4.w = f2tff(v4.w);
        *reinterpret_cast<float4*>(&kt[row * 132 + c4]) = v4;
    }

    // ---- phase 1: S[t, s] = kt[t,:] . q[s,:] ----
    for (int sc = 0; sc < 2; sc++) {
        __syncthreads();
#pragma unroll
        for (int it = 0; it < 16; it++) {
            int idx = tid + it * 256;
            int row = idx >> 5;
            int c4 = (idx & 31) << 2;
            float4 v4 = *reinterpret_cast<const float4*>(qb + (size_t)(sc * 128 + row) * SQ + c4);
            v4.x = f2tff(v4.x); v4.y = f2tff(v4.y); v4.z = f2tff(v4.z); v4.w = f2tff(v4.w);
            *reinterpret_cast<float4*>(&qs[row * 132 + c4]) = v4;
        }
        __syncthreads();
        float acc[2][4][4];
#pragma unroll
        for (int i = 0; i < 2; i++)
#pragma unroll
            for (int j = 0; j < 4; j++)
#pragma unroll
                for (int x = 0; x < 4; x++) acc[i][j][x] = 0.f;
#pragma unroll
        for (int kk = 0; kk < 128; kk += 8) {
            uint32_t a[2][4];
#pragma unroll
            for (int mi = 0; mi < 2; mi++) {
                int r0 = wm * 32 + mi * 16;
                a[mi][0] = __float_as_uint(kt[(r0 + gi) * 132 + kk + tg]);
                a[mi][1] = __float_as_uint(kt[(r0 + gi + 8) * 132 + kk + tg]);
                a[mi][2] = __float_as_uint(kt[(r0 + gi) * 132 + kk + tg + 4]);
                a[mi][3] = __float_as_uint(kt[(r0 + gi + 8) * 132 + kk + tg + 4]);
            }
#pragma unroll
            for (int ni = 0; ni < 4; ni++) {
                int c0 = wn * 32 + ni * 8;
                uint32_t b0 = __float_as_uint(qs[(c0 + gi) * 132 + kk + tg]);
                uint32_t b1 = __float_as_uint(qs[(c0 + gi) * 132 + kk + tg + 4]);
                mma8(acc[0][ni], a[0], b0, b1);
                mma8(acc[1][ni], a[1], b0, b1);
            }
        }
#pragma unroll
        for (int mi = 0; mi < 2; mi++)
#pragma unroll
            for (int ni = 0; ni < 4; ni++) {
                int row = wm * 32 + mi * 16 + gi;
                int col = sc * 128 + wn * 32 + ni * 8 + tg * 2;
                S[row * 260 + col] = acc[mi][ni][0];
                S[row * 260 + col + 1] = acc[mi][ni][1];
                S[(row + 8) * 260 + col] = acc[mi][ni][2];
                S[(row + 8) * 260 + col + 1] = acc[mi][ni][3];
            }
    }
    __syncthreads();

    // ---- phase 2: row softmax; store tf32-rounded exp, keep 1/rowsum ----
#pragma unroll
    for (int rr = 0; rr < 8; rr++) {
        int row = warp * 8 + rr;
        float m = -1e30f;
        for (int j = lane; j < 256; j += 32) m = fmaxf(m, S[row * 260 + j]);
#pragma unroll
        for (int o = 16; o; o >>= 1) m = fmaxf(m, __shfl_xor_sync(0xffffffffu, m, o));
        float sum = 0.f;
        for (int j = lane; j < 256; j += 32) {
            float e = f2tff(__expf(S[row * 260 + j] - m));
            S[row * 260 + j] = e;
            sum += e;
        }
#pragma unroll
        for (int o = 16; o; o >>= 1) sum += __shfl_xor_sync(0xffffffffu, sum, o);
        if (lane == 0) rs[row] = 1.f / sum;
    }
    __syncthreads();

    // ---- phase 3: r = exp(S) @ v, scaled by 1/rowsum ----
    float acc[2][4][4];
#pragma unroll
    for (int i = 0; i < 2; i++)
#pragma unroll
        for (int j = 0; j < 4; j++)
#pragma unroll
            for (int x = 0; x < 4; x++) acc[i][j][x] = 0.f;

    for (int sc = 0; sc < 2; sc++) {
#pragma unroll
        for (int it = 0; it < 16; it++) {
            int idx = tid + it * 256;
            int row = idx >> 5;
            int c4 = (idx & 31) << 2;
            float4 v4 = *reinterpret_cast<const float4*>(vb + (size_t)(sc * 128 + row) * SQ + c4);
            v4.x = f2tff(v4.x); v4.y = f2tff(v4.y); v4.z = f2tff(v4.z); v4.w = f2tff(v4.w);
            *reinterpret_cast<float4*>(&qs[row * 132 + c4]) = v4;
        }
        __syncthreads();
#pragma unroll
        for (int kk = 0; kk < 128; kk += 8) {
            uint32_t a[2][4];
#pragma unroll
            for (int mi = 0; mi < 2; mi++) {
                int r0 = wm * 32 + mi * 16;
                a[mi][0] = __float_as_uint(S[(r0 + gi) * 260 + sc * 128 + kk + tg]);
                a[mi][1] = __float_as_uint(S[(r0 + gi + 8) * 260 + sc * 128 + kk + tg]);
                a[mi][2] = __float_as_uint(S[(r0 + gi) * 260 + sc * 128 + kk + tg + 4]);
                a[mi][3] = __float_as_uint(S[(r0 + gi + 8) * 260 + sc * 128 + kk + tg + 4]);
            }
#pragma unroll
            for (int ni = 0; ni < 4; ni++) {
                int c0 = wn * 32 + ni * 8;
                uint32_t b0 = __float_as_uint(qs[(kk + tg) * 132 + c0 + gi]);
                uint32_t b1 = __float_as_uint(qs[(kk + tg + 4) * 132 + c0 + gi]);
                mma8(acc[0][ni], a[0], b0, b1);
                mma8(acc[1][ni], a[1], b0, b1);
            }
        }
        __syncthreads();
    }

    float* rb = r + ((size_t)b * TT + t0) * VD;
#pragma unroll
    for (int mi = 0; mi < 2; mi++)
#pragma unroll
        for (int ni = 0; ni < 4; ni++) {
            int row = wm * 32 + mi * 16 + gi;
            int col = wn * 32 + ni * 8 + tg * 2;
            float s0 = rs[row], s1 = rs[row + 8];
            rb[(size_t)row * VD + col] = acc[mi][ni][0] * s0;
            rb[(size_t)row * VD + col + 1] = acc[mi][ni][1] * s0;
            rb[(size_t)(row + 8) * VD + col] = acc[mi][ni][2] * s1;
            rb[(size_t)(row + 8) * VD + col + 1] = acc[mi][ni][3] * s1;
        }
}

// ---------------- launch ----------------
extern "C" void kernel_launch(void* const* d_in, const int* in_sizes, int n_in,
                              void* d_out, int out_size)
{
    const float* X  = (const float*)d_in[0];
    const float* Qw = (const float*)d_in[1];
    const float* Qb = (const float*)d_in[2];
    const float* Kw = (const float*)d_in[3];
    const float* Kb = (const float*)d_in[4];
    const float* Vw = (const float*)d_in[5];
    const float* Vb = (const float*)d_in[6];
    const float* W1 = (const float*)d_in[7];
    const float* b1 = (const float*)d_in[8];
    const float* W2 = (const float*)d_in[9];
    const float* b2 = (const float*)d_in[10];
    const float* W3 = (const float*)d_in[11];
    const float* b3 = (const float*)d_in[12];
    float* out = (float*)d_out;

    float *qkvp, *wp, *bp, *rp, *h1p, *h2p, *pp;
    cudaGetSymbolAddress((void**)&qkvp, g_qkv);
    cudaGetSymbolAddress((void**)&wp, g_wqkv);
    cudaGetSymbolAddress((void**)&bp, g_bqkv);
    cudaGetSymbolAddress((void**)&rp, g_r);
    cudaGetSymbolAddress((void**)&h1p, g_h1);
    cudaGetSymbolAddress((void**)&h2p, g_h2);
    cudaGetSymbolAddress((void**)&pp, g_part);

    cudaFuncSetAttribute(attn_kernel, cudaFuncAttributeMaxDynamicSharedMemorySize,
                         ATTN_SMEM_BYTES);
    cudaFuncSetAttribute(gemm_tf32_pipe, cudaFuncAttributeMaxDynamicSharedMemorySize,
                         GEMM_SMEM);

    // pack fused QKV weight + bias
    pack_qkv_kernel<<<(ND * SQ + 255) / 256, 256>>>(Qw, Kw, Vw, Qb, Kb, Vb, wp, bp);

    // fused QKV projection: [32768,128] @ [128,384] + bias, output stride 384
    gemm_tf32_pipe<<<dim3(3, 256, 1), 256, GEMM_SMEM>>>(X, wp, qkvp, bp, BB * TT, SQ, ND, 0);

    // attention
    attn_kernel<<<dim3(4, 128), 256, ATTN_SMEM_BYTES>>>(qkvp, rp);

    // MLP layer 1: [128, 32768] @ [32768, 2048], split-K 32 + sigmoid reduce
    gemm_tf32_pipe<<<dim3(FD / 128, 1, 32), 256, GEMM_SMEM>>>(rp, W1, pp, nullptr, BB, FD, TT * VD, 0);
    reduce_kernel<<<(BB * FD + 255) / 256, 256>>>(pp, b1, h1p, BB * FD, FD, 32, 1);

    // MLP layer 2: [128, 2048] @ [2048, 2048], split-K 16 + sigmoid reduce
    gemm_tf32_pipe<<<dim3(FD / 128, 1, 16), 256, GEMM_SMEM>>>(h1p, W2, pp, nullptr, BB, FD, FD, 0);
    reduce_kernel<<<(BB * FD + 255) / 256, 256>>>(pp, b2, h2p, BB * FD, FD, 16, 1);

    // MLP layer 3: [128, 2048] @ [2048, 4096], split-K 8 + bias (no act) -> out
    gemm_tf32_pipe<<<dim3(OD / 128, 1, 8), 256, GEMM_SMEM>>>(h2p, W3, pp, nullptr, BB, OD, FD, 0);
    reduce_kernel<<<(BB * OD + 255) / 256, 256>>>(pp, b3, out, BB * OD, OD, 8, 0);
}

// round 6
// speedup vs baseline: 1.2523x; 1.2523x over previous
#include <cuda_runtime.h>
#include <cuda_bf16.h>
#include <cstdint>

// ---------------- problem dims ----------------
#define BB 128
#define TT 256
#define ND 128
#define KD 128
#define VD 128
#define FD 2048
#define OD 4096   // ODIM*NDIM
#define SQ 384    // fused qkv row stride
#define K1 32768  // MLP1 K = TT*VD

// ---------------- device scratch (no allocations allowed) ----------------
__device__ float g_qkv[(size_t)BB * TT * SQ];            // fused q|k|v, stride 384
__device__ float g_wqkv[ND * SQ];                        // packed [128][384] weight
__device__ float g_bqkv[SQ];
__device__ __nv_bfloat16 g_rb[(size_t)BB * TT * VD];     // attention out, bf16 (MLP1 A)
__device__ float g_h1[BB * FD];
__device__ float g_h2[BB * FD];
__device__ float g_part[(size_t)32 * BB * FD];           // split-K partials

// ---------------- mma helpers ----------------
__device__ __forceinline__ uint32_t f2tf(float f) {
    uint32_t u;
    asm("cvt.rna.tf32.f32 %0, %1;" : "=r"(u) : "f"(f));
    return u;
}
__device__ __forceinline__ float f2tff(float f) { return __uint_as_float(f2tf(f)); }

__device__ __forceinline__ void mma8(float* c, const uint32_t* a, uint32_t b0, uint32_t b1) {
    asm volatile(
        "mma.sync.aligned.m16n8k8.row.col.f32.tf32.tf32.f32 "
        "{%0,%1,%2,%3},{%4,%5,%6,%7},{%8,%9},{%0,%1,%2,%3};"
        : "+f"(c[0]), "+f"(c[1]), "+f"(c[2]), "+f"(c[3])
        : "r"(a[0]), "r"(a[1]), "r"(a[2]), "r"(a[3]), "r"(b0), "r"(b1));
}

__device__ __forceinline__ void mma16(float* c, const uint32_t* a, uint32_t b0, uint32_t b1) {
    asm volatile(
        "mma.sync.aligned.m16n8k16.row.col.f32.bf16.bf16.f32 "
        "{%0,%1,%2,%3},{%4,%5,%6,%7},{%8,%9},{%0,%1,%2,%3};"
        : "+f"(c[0]), "+f"(c[1]), "+f"(c[2]), "+f"(c[3])
        : "r"(a[0]), "r"(a[1]), "r"(a[2]), "r"(a[3]), "r"(b0), "r"(b1));
}

__device__ __forceinline__ uint32_t pack_bf2(float lo, float hi) {
    __nv_bfloat162 h = __floats2bfloat162_rn(lo, hi);   // x=lo (k even), y=hi (k odd)
    return *reinterpret_cast<uint32_t*>(&h);
}

__device__ __forceinline__ void cp16(void* dst, const void* src) {
    uint32_t d = (uint32_t)__cvta_generic_to_shared(dst);
    asm volatile("cp.async.cg.shared.global [%0], [%1], 16;" :: "r"(d), "l"(src));
}
__device__ __forceinline__ void cp_commit() { asm volatile("cp.async.commit_group;"); }
template <int N> __device__ __forceinline__ void cp_wait() {
    asm volatile("cp.async.wait_group %0;" :: "n"(N));
}

// ---------------- pack QKV weights ----------------
__global__ void pack_qkv_kernel(
    const float* __restrict__ Qw, const float* __restrict__ Kw, const float* __restrict__ Vw,
    const float* __restrict__ Qb, const float* __restrict__ Kb, const float* __restrict__ Vb,
    float* __restrict__ w, float* __restrict__ bia)
{
    int idx = blockIdx.x * 256 + threadIdx.x;
    if (idx < ND * SQ) {
        int k = idx / SQ, c = idx % SQ;
        float v;
        if (c < 128)       v = Qw[k * 128 + c];
        else if (c < 256)  v = Kw[k * 128 + c - 128];
        else               v = Vw[k * 128 + c - 256];
        w[idx] = v;
    }
    if (idx < SQ) {
        float v;
        if (idx < 128)      v = Qb[idx];
        else if (idx < 256) v = Kb[idx - 128];
        else                v = Vb[idx - 256];
        bia[idx] = v;
    }
}

// ---------------- generic pipelined tf32 GEMM (R4 config: 64x64 warps) ----------------
#define ASTRIDE 36
#define BSTRIDE 136
#define GEMM_SMEM ((2 * 128 * ASTRIDE + 2 * 32 * BSTRIDE) * 4)

__global__ __launch_bounds__(128, 2) void gemm_tf32_pipe(
    const float* __restrict__ A, const float* __restrict__ Bm,
    float* __restrict__ C, const float* __restrict__ bias,
    int M, int N, int K, int act)
{
    extern __shared__ float smp[];
    float* As = smp;                          // [2][128][ASTRIDE]
    float* Bs = smp + 2 * 128 * ASTRIDE;      // [2][32][BSTRIDE]

    const int splits = gridDim.z;
    const int kchunk = K / splits;
    const int kbeg = blockIdx.z * kchunk;
    const int m0 = blockIdx.y * 128;
    const int n0 = blockIdx.x * 128;
    const int tid = threadIdx.x;
    const int warp = tid >> 5, lane = tid & 31;
    const int wm = warp & 1, wn = warp >> 1;      // 2(M) x 2(N); warp tile 64x64
    const int gi = lane >> 2, tg = lane & 3;

    float acc[4][8][4];
#pragma unroll
    for (int i = 0; i < 4; i++)
#pragma unroll
        for (int j = 0; j < 8; j++)
#pragma unroll
            for (int x = 0; x < 4; x++) acc[i][j][x] = 0.f;

    auto stage = [&](int s, int kb) {
        float* as = As + s * (128 * ASTRIDE);
        float* bs = Bs + s * (32 * BSTRIDE);
#pragma unroll
        for (int it = 0; it < 8; it++) {
            int flat = it * 128 + tid;
            int row = flat >> 3, c4 = (flat & 7) << 2;
            cp16(&as[row * ASTRIDE + c4], A + (size_t)(m0 + row) * K + kb + c4);
        }
#pragma unroll
        for (int it = 0; it < 8; it++) {
            int flat = it * 128 + tid;
            int row = flat >> 5, c4 = (flat & 31) << 2;
            cp16(&bs[row * BSTRIDE + c4], Bm + (size_t)(kb + row) * N + n0 + c4);
        }
        cp_commit();
    };

    const int nsteps = kchunk / 32;
    stage(0, kbeg);

    for (int s = 0; s < nsteps; s++) {
        if (s + 1 < nsteps) { stage((s + 1) & 1, kbeg + (s + 1) * 32); cp_wait<1>(); }
        else cp_wait<0>();
        __syncthreads();
        float* as = As + (s & 1) * (128 * ASTRIDE);
        float* bs = Bs + (s & 1) * (32 * BSTRIDE);
#pragma unroll
        for (int kk = 0; kk < 32; kk += 8) {
            uint32_t a[4][4];
#pragma unroll
            for (int mi = 0; mi < 4; mi++) {
                int r0 = wm * 64 + mi * 16;
                a[mi][0] = f2tf(as[(r0 + gi) * ASTRIDE + kk + tg]);
                a[mi][1] = f2tf(as[(r0 + gi + 8) * ASTRIDE + kk + tg]);
                a[mi][2] = f2tf(as[(r0 + gi) * ASTRIDE + kk + tg + 4]);
                a[mi][3] = f2tf(as[(r0 + gi + 8) * ASTRIDE + kk + tg + 4]);
            }
            uint32_t b[8][2];
#pragma unroll
            for (int ni = 0; ni < 8; ni++) {
                int c0 = wn * 64 + ni * 8;
                b[ni][0] = f2tf(bs[(kk + tg) * BSTRIDE + c0 + gi]);
                b[ni][1] = f2tf(bs[(kk + tg + 4) * BSTRIDE + c0 + gi]);
            }
#pragma unroll
            for (int mi = 0; mi < 4; mi++)
#pragma unroll
                for (int ni = 0; ni < 8; ni++)
                    mma8(acc[mi][ni], a[mi], b[ni][0], b[ni][1]);
        }
        __syncthreads();
    }

    const bool fused = (splits == 1);
    float* Cout = C + (size_t)blockIdx.z * (size_t)M * (size_t)N;
#pragma unroll
    for (int mi = 0; mi < 4; mi++) {
#pragma unroll
        for (int ni = 0; ni < 8; ni++) {
            int row = m0 + wm * 64 + mi * 16 + gi;
            int col = n0 + wn * 64 + ni * 8 + tg * 2;
            float c0 = acc[mi][ni][0], c1 = acc[mi][ni][1];
            float c2 = acc[mi][ni][2], c3 = acc[mi][ni][3];
            if (fused) {
                float bv0 = bias ? bias[col] : 0.f;
                float bv1 = bias ? bias[col + 1] : 0.f;
                c0 += bv0; c1 += bv1; c2 += bv0; c3 += bv1;
                if (act == 1) {
                    c0 = 1.f / (1.f + __expf(-c0));
                    c1 = 1.f / (1.f + __expf(-c1));
                    c2 = 1.f / (1.f + __expf(-c2));
                    c3 = 1.f / (1.f + __expf(-c3));
                }
            }
            Cout[(size_t)row * N + col] = c0;
            Cout[(size_t)row * N + col + 1] = c1;
            Cout[(size_t)(row + 8) * N + col] = c2;
            Cout[(size_t)(row + 8) * N + col + 1] = c3;
        }
    }
}

// ---------------- MLP1 bf16 GEMM ----------------
// P[z][128][2048] partial = A_bf16[128, kchunk] @ bf16(W1[kchunk, 2048-tile])
// CTA 128x128, 128 threads, 4 warps 64x64, kstep 64 (4x k16), double-buffered.
// A (bf16, pre-written by attn) via cp.async; W1 (fp32) via LDG->cvt/pack->STS.
#define M1_ASTR 72                      // bf16 elems per A row (64+8)
#define M1_BSTR 136                     // uint32 per B pair-row (128+8)
#define M1_AELEM (128 * M1_ASTR)        // bf16 per stage
#define M1_BELEM (32 * M1_BSTR)         // uint32 per stage
#define M1_SMEM (2 * (M1_AELEM * 2 + M1_BELEM * 4))
#define M1_SPLITS 32
#define M1_NSTEP 16                     // kchunk 1024 / 64

__global__ __launch_bounds__(128, 2) void mlp1_bf16_kernel(
    const __nv_bfloat16* __restrict__ A,   // [128][32768]
    const float* __restrict__ Bm,          // W1 [32768][2048]
    float* __restrict__ P)
{
    extern __shared__ char smraw[];
    __nv_bfloat16* As = reinterpret_cast<__nv_bfloat16*>(smraw);          // [2][128][72]
    uint32_t* Bs = reinterpret_cast<uint32_t*>(smraw + 2 * M1_AELEM * 2); // [2][32][136]

    const int kbeg = blockIdx.z * (K1 / M1_SPLITS);
    const int n0 = blockIdx.x * 128;
    const int tid = threadIdx.x;
    const int warp = tid >> 5, lane = tid & 31;
    const int wm = warp & 1, wn = warp >> 1;      // 2x2 warps, 64x64 tiles
    const int gi = lane >> 2, tg = lane & 3;

    float acc[4][8][4];
#pragma unroll
    for (int i = 0; i < 4; i++)
#pragma unroll
        for (int j = 0; j < 8; j++)
#pragma unroll
            for (int x = 0; x < 4; x++) acc[i][j][x] = 0.f;

    float4 blo[8], bhi[8];   // W1 prefetch: 8 pair-chunks per thread

    auto ldgB = [&](int kb) {
#pragma unroll
        for (int j = 0; j < 8; j++) {
            int c = j * 128 + tid;                 // 1024 pair-chunks
            int pr = c >> 5;                       // pair-row 0..31
            int colc = (c & 31) << 2;              // float4 col
            const float* p0 = Bm + (size_t)(kb + 2 * pr) * FD + n0 + colc;
            blo[j] = *reinterpret_cast<const float4*>(p0);
            bhi[j] = *reinterpret_cast<const float4*>(p0 + FD);
        }
    };
    auto stsB = [&](int s) {
        uint32_t* bs = Bs + s * M1_BELEM;
#pragma unroll
        for (int j = 0; j < 8; j++) {
            int c = j * 128 + tid;
            int pr = c >> 5;
            int colc = (c & 31) << 2;
            uint4 u;
            u.x = pack_bf2(blo[j].x, bhi[j].x);
            u.y = pack_bf2(blo[j].y, bhi[j].y);
            u.z = pack_bf2(blo[j].z, bhi[j].z);
            u.w = pack_bf2(blo[j].w, bhi[j].w);
            *reinterpret_cast<uint4*>(&bs[pr * M1_BSTR + colc]) = u;
        }
    };
    auto stageA = [&](int s, int kb) {
        __nv_bfloat16* as = As + s * M1_AELEM;
#pragma unroll
        for (int it = 0; it < 8; it++) {
            int flat = it * 128 + tid;             // 1024 chunks of 16B (8 bf16)
            int row = flat >> 3, ch = (flat & 7) << 3;
            cp16(&as[row * M1_ASTR + ch], A + (size_t)row * K1 + kb + ch);
        }
        cp_commit();
    };

    stageA(0, kbeg);
    ldgB(kbeg);

    for (int s = 0; s < M1_NSTEP; s++) {
        const int kb_next = kbeg + (s + 1) * 64;
        if (s + 1 < M1_NSTEP) stageA((s + 1) & 1, kb_next);
        stsB(s & 1);
        if (s + 1 < M1_NSTEP) cp_wait<1>(); else cp_wait<0>();
        __syncthreads();
        if (s + 1 < M1_NSTEP) ldgB(kb_next);

        const uint32_t* a32 = reinterpret_cast<const uint32_t*>(As) + (s & 1) * (M1_AELEM / 2);
        const uint32_t* bsp = Bs + (s & 1) * M1_BELEM;
#pragma unroll
        for (int kk2 = 0; kk2 < 32; kk2 += 8) {    // kk2 = k/2; 4 x k16 steps
            uint32_t a[4][4];
#pragma unroll
            for (int mi = 0; mi < 4; mi++) {
                int r0 = wm * 64 + mi * 16;
                a[mi][0] = a32[(r0 + gi) * 36 + kk2 + tg];
                a[mi][1] = a32[(r0 + gi + 8) * 36 + kk2 + tg];
                a[mi][2] = a32[(r0 + gi) * 36 + kk2 + tg + 4];
                a[mi][3] = a32[(r0 + gi + 8) * 36 + kk2 + tg + 4];
            }
            uint32_t b[8][2];
#pragma unroll
            for (int ni = 0; ni < 8; ni++) {
                int c0 = wn * 64 + ni * 8;
                b[ni][0] = bsp[(kk2 + tg) * M1_BSTR + c0 + gi];
                b[ni][1] = bsp[(kk2 + tg + 4) * M1_BSTR + c0 + gi];
            }
#pragma unroll
            for (int mi = 0; mi < 4; mi++)
#pragma unroll
                for (int ni = 0; ni < 8; ni++)
                    mma16(acc[mi][ni], a[mi], b[ni][0], b[ni][1]);
        }
        __syncthreads();
    }

    float* Cout = P + (size_t)blockIdx.z * (size_t)BB * (size_t)FD;
#pragma unroll
    for (int mi = 0; mi < 4; mi++) {
#pragma unroll
        for (int ni = 0; ni < 8; ni++) {
            int row = wm * 64 + mi * 16 + gi;
            int col = n0 + wn * 64 + ni * 8 + tg * 2;
            Cout[(size_t)row * FD + col] = acc[mi][ni][0];
            Cout[(size_t)row * FD + col + 1] = acc[mi][ni][1];
            Cout[(size_t)(row + 8) * FD + col] = acc[mi][ni][2];
            Cout[(size_t)(row + 8) * FD + col + 1] = acc[mi][ni][3];
        }
    }
}

// ---------------- split reduce + bias + activation ----------------
__global__ __launch_bounds__(256) void reduce_kernel(
    const float* __restrict__ part, const float* __restrict__ bias,
    float* __restrict__ out, int MN, int N, int splits, int act)
{
    int i = blockIdx.x * 256 + threadIdx.x;
    if (i >= MN) return;
    float s = 0.f;
    for (int z = 0; z < splits; z++) s += part[(size_t)z * MN + i];
    s += bias[i % N];
    if (act) s = 1.f / (1.f + __expf(-s));
    out[i] = s;
}

// ---------------- attention: softmax(K Q^T) V, bf16 output ----------------
#define ATTN_SMEM_BYTES ((64 * 132 + 64 * 260 + 128 * 132 + 64) * 4)

__global__ __launch_bounds__(256) void attn_kernel(
    const float* __restrict__ qkv, __nv_bfloat16* __restrict__ r)
{
    extern __shared__ float sm[];
    float* kt = sm;                    // [64][132]
    float* S = sm + 64 * 132;          // [64][260]
    float* qs = S + 64 * 260;          // [128][132]
    float* rs = qs + 128 * 132;        // [64]

    const int b = blockIdx.y;
    const int t0 = blockIdx.x * 64;
    const float* qb = qkv + (size_t)b * TT * SQ;
    const float* kb = qkv + ((size_t)b * TT + t0) * SQ + 128;
    const float* vb = qkv + (size_t)b * TT * SQ + 256;
    const int tid = threadIdx.x, warp = tid >> 5, lane = tid & 31;
    const int gi = lane >> 2, tg = lane & 3;
    const int wm = warp & 1, wn = warp >> 1;

#pragma unroll
    for (int it = 0; it < 8; it++) {
        int idx = tid + it * 256;
        int row = idx >> 5;
        int c4 = (idx & 31) << 2;
        float4 v4 = *reinterpret_cast<const float4*>(kb + (size_t)row * SQ + c4);
        v4.x = f2tff(v4.x); v4.y = f2tff(v4.y); v4.z = f2tff(v4.z); v4.w = f2tff(v4.w);
        *reinterpret_cast<float4*>(&kt[row * 132 + c4]) = v4;
    }

    for (int sc = 0; sc < 2; sc++) {
        __syncthreads();
#pragma unroll
        for (int it = 0; it < 16; it++) {
            int idx = tid + it * 256;
            int row = idx >> 5;
            int c4 = (idx & 31) << 2;
            float4 v4 = *reinterpret_cast<const float4*>(qb + (size_t)(sc * 128 + row) * SQ + c4);
            v4.x = f2tff(v4.x); v4.y = f2tff(v4.y); v4.z = f2tff(v4.z); v4.w = f2tff(v4.w);
            *reinterpret_cast<float4*>(&qs[row * 132 + c4]) = v4;
        }
        __syncthreads();
        float acc[2][4][4];
#pragma unroll
        for (int i = 0; i < 2; i++)
#pragma unroll
            for (int j = 0; j < 4; j++)
#pragma unroll
                for (int x = 0; x < 4; x++) acc[i][j][x] = 0.f;
#pragma unroll
        for (int kk = 0; kk < 128; kk += 8) {
            uint32_t a[2][4];
#pragma unroll
            for (int mi = 0; mi < 2; mi++) {
                int r0 = wm * 32 + mi * 16;
                a[mi][0] = __float_as_uint(kt[(r0 + gi) * 132 + kk + tg]);
                a[mi][1] = __float_as_uint(kt[(r0 + gi + 8) * 132 + kk + tg]);
                a[mi][2] = __float_as_uint(kt[(r0 + gi) * 132 + kk + tg + 4]);
                a[mi][3] = __float_as_uint(kt[(r0 + gi + 8) * 132 + kk + tg + 4]);
            }
#pragma unroll
            for (int ni = 0; ni < 4; ni++) {
                int c0 = wn * 32 + ni * 8;
                uint32_t b0 = __float_as_uint(qs[(c0 + gi) * 132 + kk + tg]);
                uint32_t b1 = __float_as_uint(qs[(c0 + gi) * 132 + kk + tg + 4]);
                mma8(acc[0][ni], a[0], b0, b1);
                mma8(acc[1][ni], a[1], b0, b1);
            }
        }
#pragma unroll
        for (int mi = 0; mi < 2; mi++)
#pragma unroll
            for (int ni = 0; ni < 4; ni++) {
                int row = wm * 32 + mi * 16 + gi;
                int col = sc * 128 + wn * 32 + ni * 8 + tg * 2;
                S[row * 260 + col] = acc[mi][ni][0];
                S[row * 260 + col + 1] = acc[mi][ni][1];
                S[(row + 8) * 260 + col] = acc[mi][ni][2];
                S[(row + 8) * 260 + col + 1] = acc[mi][ni][3];
            }
    }
    __syncthreads();

#pragma unroll
    for (int rr = 0; rr < 8; rr++) {
        int row = warp * 8 + rr;
        float m = -1e30f;
        for (int j = lane; j < 256; j += 32) m = fmaxf(m, S[row * 260 + j]);
#pragma unroll
        for (int o = 16; o; o >>= 1) m = fmaxf(m, __shfl_xor_sync(0xffffffffu, m, o));
        float sum = 0.f;
        for (int j = lane; j < 256; j += 32) {
            float e = f2tff(__expf(S[row * 260 + j] - m));
            S[row * 260 + j] = e;
            sum += e;
        }
#pragma unroll
        for (int o = 16; o; o >>= 1) sum += __shfl_xor_sync(0xffffffffu, sum, o);
        if (lane == 0) rs[row] = 1.f / sum;
    }
    __syncthreads();

    float acc[2][4][4];
#pragma unroll
    for (int i = 0; i < 2; i++)
#pragma unroll
        for (int j = 0; j < 4; j++)
#pragma unroll
            for (int x = 0; x < 4; x++) acc[i][j][x] = 0.f;

    for (int sc = 0; sc < 2; sc++) {
#pragma unroll
        for (int it = 0; it < 16; it++) {
            int idx = tid + it * 256;
            int row = idx >> 5;
            int c4 = (idx & 31) << 2;
            float4 v4 = *reinterpret_cast<const float4*>(vb + (size_t)(sc * 128 + row) * SQ + c4);
            v4.x = f2tff(v4.x); v4.y = f2tff(v4.y); v4.z = f2tff(v4.z); v4.w = f2tff(v4.w);
            *reinterpret_cast<float4*>(&qs[row * 132 + c4]) = v4;
        }
        __syncthreads();
#pragma unroll
        for (int kk = 0; kk < 128; kk += 8) {
            uint32_t a[2][4];
#pragma unroll
            for (int mi = 0; mi < 2; mi++) {
                int r0 = wm * 32 + mi * 16;
                a[mi][0] = __float_as_uint(S[(r0 + gi) * 260 + sc * 128 + kk + tg]);
                a[mi][1] = __float_as_uint(S[(r0 + gi + 8) * 260 + sc * 128 + kk + tg]);
                a[mi][2] = __float_as_uint(S[(r0 + gi) * 260 + sc * 128 + kk + tg + 4]);
                a[mi][3] = __float_as_uint(S[(r0 + gi + 8) * 260 + sc * 128 + kk + tg + 4]);
            }
#pragma unroll
            for (int ni = 0; ni < 4; ni++) {
                int c0 = wn * 32 + ni * 8;
                uint32_t b0 = __float_as_uint(qs[(kk + tg) * 132 + c0 + gi]);
                uint32_t b1 = __float_as_uint(qs[(kk + tg + 4) * 132 + c0 + gi]);
                mma8(acc[0][ni], a[0], b0, b1);
                mma8(acc[1][ni], a[1], b0, b1);
            }
        }
        __syncthreads();
    }

    __nv_bfloat16* rb = r + ((size_t)b * TT + t0) * VD;
#pragma unroll
    for (int mi = 0; mi < 2; mi++)
#pragma unroll
        for (int ni = 0; ni < 4; ni++) {
            int row = wm * 32 + mi * 16 + gi;
            int col = wn * 32 + ni * 8 + tg * 2;
            float s0 = rs[row], s1 = rs[row + 8];
            rb[(size_t)row * VD + col]     = __float2bfloat16(acc[mi][ni][0] * s0);
            rb[(size_t)row * VD + col + 1] = __float2bfloat16(acc[mi][ni][1] * s0);
            rb[(size_t)(row + 8) * VD + col]     = __float2bfloat16(acc[mi][ni][2] * s1);
            rb[(size_t)(row + 8) * VD + col + 1] = __float2bfloat16(acc[mi][ni][3] * s1);
        }
}

// ---------------- launch ----------------
extern "C" void kernel_launch(void* const* d_in, const int* in_sizes, int n_in,
                              void* d_out, int out_size)
{
    const float* X  = (const float*)d_in[0];
    const float* Qw = (const float*)d_in[1];
    const float* Qb = (const float*)d_in[2];
    const float* Kw = (const float*)d_in[3];
    const float* Kb = (const float*)d_in[4];
    const float* Vw = (const float*)d_in[5];
    const float* Vb = (const float*)d_in[6];
    const float* W1 = (const float*)d_in[7];
    const float* b1 = (const float*)d_in[8];
    const float* W2 = (const float*)d_in[9];
    const float* b2 = (const float*)d_in[10];
    const float* W3 = (const float*)d_in[11];
    const float* b3 = (const float*)d_in[12];
    float* out = (float*)d_out;

    float *qkvp, *wp, *bp, *h1p, *h2p, *pp;
    __nv_bfloat16* rbp;
    cudaGetSymbolAddress((void**)&qkvp, g_qkv);
    cudaGetSymbolAddress((void**)&wp, g_wqkv);
    cudaGetSymbolAddress((void**)&bp, g_bqkv);
    cudaGetSymbolAddress((void**)&rbp, g_rb);
    cudaGetSymbolAddress((void**)&h1p, g_h1);
    cudaGetSymbolAddress((void**)&h2p, g_h2);
    cudaGetSymbolAddress((void**)&pp, g_part);

    cudaFuncSetAttribute(attn_kernel, cudaFuncAttributeMaxDynamicSharedMemorySize,
                         ATTN_SMEM_BYTES);
    cudaFuncSetAttribute(gemm_tf32_pipe, cudaFuncAttributeMaxDynamicSharedMemorySize,
                         GEMM_SMEM);
    cudaFuncSetAttribute(mlp1_bf16_kernel, cudaFuncAttributeMaxDynamicSharedMemorySize,
                         M1_SMEM);

    // pack fused QKV weight + bias
    pack_qkv_kernel<<<(ND * SQ + 255) / 256, 256>>>(Qw, Kw, Vw, Qb, Kb, Vb, wp, bp);

    // fused QKV projection: [32768,128] @ [128,384] + bias, output stride 384
    gemm_tf32_pipe<<<dim3(3, 256, 1), 128, GEMM_SMEM>>>(X, wp, qkvp, bp, BB * TT, SQ, ND, 0);

    // attention (writes r as bf16)
    attn_kernel<<<dim3(4, 128), 256, ATTN_SMEM_BYTES>>>(qkvp, rbp);

    // MLP layer 1 (bf16 tensor): [128, 32768] @ [32768, 2048], split-K 32 + sigmoid reduce
    mlp1_bf16_kernel<<<dim3(FD / 128, 1, M1_SPLITS), 128, M1_SMEM>>>(rbp, W1, pp);
    reduce_kernel<<<(BB * FD + 255) / 256, 256>>>(pp, b1, h1p, BB * FD, FD, M1_SPLITS, 1);

    // MLP layer 2: [128, 2048] @ [2048, 2048], split-K 16 + sigmoid reduce
    gemm_tf32_pipe<<<dim3(FD / 128, 1, 16), 128, GEMM_SMEM>>>(h1p, W2, pp, nullptr, BB, FD, FD, 0);
    reduce_kernel<<<(BB * FD + 255) / 256, 256>>>(pp, b2, h2p, BB * FD, FD, 16, 1);

    // MLP layer 3: [128, 2048] @ [2048, 4096], split-K 8 + bias (no act) -> out
    gemm_tf32_pipe<<<dim3(OD / 128, 1, 8), 128, GEMM_SMEM>>>(h2p, W3, pp, nullptr, BB, OD, FD, 0);
    reduce_kernel<<<(BB * OD + 255) / 256, 256>>>(pp, b3, out, BB * OD, OD, 8, 0);
}

// round 7
// speedup vs baseline: 1.2858x; 1.0268x over previous
#include <cuda_runtime.h>
#include <cuda_bf16.h>
#include <cstdint>

// ---------------- problem dims ----------------
#define BB 128
#define TT 256
#define ND 128
#define KD 128
#define VD 128
#define FD 2048
#define OD 4096   // ODIM*NDIM
#define SQ 384    // fused qkv row stride
#define K1 32768  // MLP1 K = TT*VD

// ---------------- device scratch (no allocations allowed) ----------------
__device__ float g_qkv[(size_t)BB * TT * SQ];            // fused q|k|v, stride 384
__device__ float g_wqkv[ND * SQ];                        // packed [128][384] weight
__device__ float g_bqkv[SQ];
__device__ __nv_bfloat16 g_rb[(size_t)BB * TT * VD];     // attention out, bf16 (MLP1 A)
__device__ float g_h1[BB * FD];
__device__ float g_h2[BB * FD];
__device__ float g_part[(size_t)32 * BB * FD];           // split-K partials

// ---------------- mma helpers ----------------
__device__ __forceinline__ uint32_t f2tf(float f) {
    uint32_t u;
    asm("cvt.rna.tf32.f32 %0, %1;" : "=r"(u) : "f"(f));
    return u;
}
__device__ __forceinline__ float f2tff(float f) { return __uint_as_float(f2tf(f)); }

__device__ __forceinline__ void mma8(float* c, const uint32_t* a, uint32_t b0, uint32_t b1) {
    asm volatile(
        "mma.sync.aligned.m16n8k8.row.col.f32.tf32.tf32.f32 "
        "{%0,%1,%2,%3},{%4,%5,%6,%7},{%8,%9},{%0,%1,%2,%3};"
        : "+f"(c[0]), "+f"(c[1]), "+f"(c[2]), "+f"(c[3])
        : "r"(a[0]), "r"(a[1]), "r"(a[2]), "r"(a[3]), "r"(b0), "r"(b1));
}

__device__ __forceinline__ void mma16(float* c, const uint32_t* a, uint32_t b0, uint32_t b1) {
    asm volatile(
        "mma.sync.aligned.m16n8k16.row.col.f32.bf16.bf16.f32 "
        "{%0,%1,%2,%3},{%4,%5,%6,%7},{%8,%9},{%0,%1,%2,%3};"
        : "+f"(c[0]), "+f"(c[1]), "+f"(c[2]), "+f"(c[3])
        : "r"(a[0]), "r"(a[1]), "r"(a[2]), "r"(a[3]), "r"(b0), "r"(b1));
}

__device__ __forceinline__ uint32_t pack_bf2(float lo, float hi) {
    __nv_bfloat162 h = __floats2bfloat162_rn(lo, hi);   // x=lo (k even), y=hi (k odd)
    return *reinterpret_cast<uint32_t*>(&h);
}

__device__ __forceinline__ void cp16(void* dst, const void* src) {
    uint32_t d = (uint32_t)__cvta_generic_to_shared(dst);
    asm volatile("cp.async.cg.shared.global [%0], [%1], 16;" :: "r"(d), "l"(src));
}
__device__ __forceinline__ void cp_commit() { asm volatile("cp.async.commit_group;"); }
template <int N> __device__ __forceinline__ void cp_wait() {
    asm volatile("cp.async.wait_group %0;" :: "n"(N));
}

// ---------------- pack QKV weights ----------------
__global__ void pack_qkv_kernel(
    const float* __restrict__ Qw, const float* __restrict__ Kw, const float* __restrict__ Vw,
    const float* __restrict__ Qb, const float* __restrict__ Kb, const float* __restrict__ Vb,
    float* __restrict__ w, float* __restrict__ bia)
{
    int idx = blockIdx.x * 256 + threadIdx.x;
    if (idx < ND * SQ) {
        int k = idx / SQ, c = idx % SQ;
        float v;
        if (c < 128)       v = Qw[k * 128 + c];
        else if (c < 256)  v = Kw[k * 128 + c - 128];
        else               v = Vw[k * 128 + c - 256];
        w[idx] = v;
    }
    if (idx < SQ) {
        float v;
        if (idx < 128)      v = Qb[idx];
        else if (idx < 256) v = Kb[idx - 128];
        else                v = Vb[idx - 256];
        bia[idx] = v;
    }
}

// ---------------- generic pipelined tf32 GEMM (64x64 warps) ----------------
#define ASTRIDE 36
#define BSTRIDE 136
#define GEMM_SMEM ((2 * 128 * ASTRIDE + 2 * 32 * BSTRIDE) * 4)

__global__ __launch_bounds__(128, 2) void gemm_tf32_pipe(
    const float* __restrict__ A, const float* __restrict__ Bm,
    float* __restrict__ C, const float* __restrict__ bias,
    int M, int N, int K, int act)
{
    extern __shared__ float smp[];
    float* As = smp;                          // [2][128][ASTRIDE]
    float* Bs = smp + 2 * 128 * ASTRIDE;      // [2][32][BSTRIDE]

    const int splits = gridDim.z;
    const int kchunk = K / splits;
    const int kbeg = blockIdx.z * kchunk;
    const int m0 = blockIdx.y * 128;
    const int n0 = blockIdx.x * 128;
    const int tid = threadIdx.x;
    const int warp = tid >> 5, lane = tid & 31;
    const int wm = warp & 1, wn = warp >> 1;      // 2(M) x 2(N); warp tile 64x64
    const int gi = lane >> 2, tg = lane & 3;

    float acc[4][8][4];
#pragma unroll
    for (int i = 0; i < 4; i++)
#pragma unroll
        for (int j = 0; j < 8; j++)
#pragma unroll
            for (int x = 0; x < 4; x++) acc[i][j][x] = 0.f;

    auto stage = [&](int s, int kb) {
        float* as = As + s * (128 * ASTRIDE);
        float* bs = Bs + s * (32 * BSTRIDE);
#pragma unroll
        for (int it = 0; it < 8; it++) {
            int flat = it * 128 + tid;
            int row = flat >> 3, c4 = (flat & 7) << 2;
            cp16(&as[row * ASTRIDE + c4], A + (size_t)(m0 + row) * K + kb + c4);
        }
#pragma unroll
        for (int it = 0; it < 8; it++) {
            int flat = it * 128 + tid;
            int row = flat >> 5, c4 = (flat & 31) << 2;
            cp16(&bs[row * BSTRIDE + c4], Bm + (size_t)(kb + row) * N + n0 + c4);
        }
        cp_commit();
    };

    const int nsteps = kchunk / 32;
    stage(0, kbeg);

    for (int s = 0; s < nsteps; s++) {
        if (s + 1 < nsteps) { stage((s + 1) & 1, kbeg + (s + 1) * 32); cp_wait<1>(); }
        else cp_wait<0>();
        __syncthreads();
        float* as = As + (s & 1) * (128 * ASTRIDE);
        float* bs = Bs + (s & 1) * (32 * BSTRIDE);
#pragma unroll
        for (int kk = 0; kk < 32; kk += 8) {
            uint32_t a[4][4];
#pragma unroll
            for (int mi = 0; mi < 4; mi++) {
                int r0 = wm * 64 + mi * 16;
                a[mi][0] = f2tf(as[(r0 + gi) * ASTRIDE + kk + tg]);
                a[mi][1] = f2tf(as[(r0 + gi + 8) * ASTRIDE + kk + tg]);
                a[mi][2] = f2tf(as[(r0 + gi) * ASTRIDE + kk + tg + 4]);
                a[mi][3] = f2tf(as[(r0 + gi + 8) * ASTRIDE + kk + tg + 4]);
            }
            uint32_t b[8][2];
#pragma unroll
            for (int ni = 0; ni < 8; ni++) {
                int c0 = wn * 64 + ni * 8;
                b[ni][0] = f2tf(bs[(kk + tg) * BSTRIDE + c0 + gi]);
                b[ni][1] = f2tf(bs[(kk + tg + 4) * BSTRIDE + c0 + gi]);
            }
#pragma unroll
            for (int mi = 0; mi < 4; mi++)
#pragma unroll
                for (int ni = 0; ni < 8; ni++)
                    mma8(acc[mi][ni], a[mi], b[ni][0], b[ni][1]);
        }
        __syncthreads();
    }

    const bool fused = (splits == 1);
    float* Cout = C + (size_t)blockIdx.z * (size_t)M * (size_t)N;
#pragma unroll
    for (int mi = 0; mi < 4; mi++) {
#pragma unroll
        for (int ni = 0; ni < 8; ni++) {
            int row = m0 + wm * 64 + mi * 16 + gi;
            int col = n0 + wn * 64 + ni * 8 + tg * 2;
            float c0 = acc[mi][ni][0], c1 = acc[mi][ni][1];
            float c2 = acc[mi][ni][2], c3 = acc[mi][ni][3];
            if (fused) {
                float bv0 = bias ? bias[col] : 0.f;
                float bv1 = bias ? bias[col + 1] : 0.f;
                c0 += bv0; c1 += bv1; c2 += bv0; c3 += bv1;
                if (act == 1) {
                    c0 = 1.f / (1.f + __expf(-c0));
                    c1 = 1.f / (1.f + __expf(-c1));
                    c2 = 1.f / (1.f + __expf(-c2));
                    c3 = 1.f / (1.f + __expf(-c3));
                }
            }
            Cout[(size_t)row * N + col] = c0;
            Cout[(size_t)row * N + col + 1] = c1;
            Cout[(size_t)(row + 8) * N + col] = c2;
            Cout[(size_t)(row + 8) * N + col + 1] = c3;
        }
    }
}

// ---------------- MLP1 bf16 GEMM, CTA 128x64, 3 CTAs/SM ----------------
#define M1_ASTR 72                      // bf16 per A row (64+8)
#define M1_BSTR 72                      // u32 per B pair-row (64+8)
#define M1_AELEM (128 * M1_ASTR)        // bf16 per stage
#define M1_BELEM (32 * M1_BSTR)         // u32 per stage
#define M1_SMEM (2 * (M1_AELEM * 2 + M1_BELEM * 4))
#define M1_SPLITS 32
#define M1_NSTEP 16                     // kchunk 1024 / 64

__global__ __launch_bounds__(128, 3) void mlp1_bf16_kernel(
    const __nv_bfloat16* __restrict__ A,   // [128][32768]
    const float* __restrict__ Bm,          // W1 [32768][2048]
    float* __restrict__ P)
{
    extern __shared__ char smraw[];
    __nv_bfloat16* As = reinterpret_cast<__nv_bfloat16*>(smraw);          // [2][128][72]
    uint32_t* Bs = reinterpret_cast<uint32_t*>(smraw + 2 * M1_AELEM * 2); // [2][32][72]

    const int kbeg = blockIdx.z * (K1 / M1_SPLITS);
    const int n0 = blockIdx.x * 64;
    const int tid = threadIdx.x;
    const int warp = tid >> 5, lane = tid & 31;
    const int wm = warp & 1, wn = warp >> 1;      // 2x2 warps, 64x32 tiles
    const int gi = lane >> 2, tg = lane & 3;

    float acc[4][4][4];
#pragma unroll
    for (int i = 0; i < 4; i++)
#pragma unroll
        for (int j = 0; j < 4; j++)
#pragma unroll
            for (int x = 0; x < 4; x++) acc[i][j][x] = 0.f;

    float4 blo[4], bhi[4];   // W1 prefetch: 4 pair-chunks per thread

    auto ldgB = [&](int kb) {
#pragma unroll
        for (int j = 0; j < 4; j++) {
            int c = j * 128 + tid;                 // 512 pair-chunks (32 pr x 16 colc)
            int pr = c >> 4;                       // pair-row 0..31
            int colc = (c & 15) << 2;              // float4 col 0..60
            const float* p0 = Bm + (size_t)(kb + 2 * pr) * FD + n0 + colc;
            blo[j] = *reinterpret_cast<const float4*>(p0);
            bhi[j] = *reinterpret_cast<const float4*>(p0 + FD);
        }
    };
    auto stsB = [&](int s) {
        uint32_t* bs = Bs + s * M1_BELEM;
#pragma unroll
        for (int j = 0; j < 4; j++) {
            int c = j * 128 + tid;
            int pr = c >> 4;
            int colc = (c & 15) << 2;
            uint4 u;
            u.x = pack_bf2(blo[j].x, bhi[j].x);
            u.y = pack_bf2(blo[j].y, bhi[j].y);
            u.z = pack_bf2(blo[j].z, bhi[j].z);
            u.w = pack_bf2(blo[j].w, bhi[j].w);
            *reinterpret_cast<uint4*>(&bs[pr * M1_BSTR + colc]) = u;
        }
    };
    auto stageA = [&](int s, int kb) {
        __nv_bfloat16* as = As + s * M1_AELEM;
#pragma unroll
        for (int it = 0; it < 8; it++) {
            int flat = it * 128 + tid;             // 1024 chunks of 16B (8 bf16)
            int row = flat >> 3, ch = (flat & 7) << 3;
            cp16(&as[row * M1_ASTR + ch], A + (size_t)row * K1 + kb + ch);
        }
        cp_commit();
    };

    stageA(0, kbeg);
    ldgB(kbeg);

    for (int s = 0; s < M1_NSTEP; s++) {
        const int kb_next = kbeg + (s + 1) * 64;
        if (s + 1 < M1_NSTEP) stageA((s + 1) & 1, kb_next);
        stsB(s & 1);
        if (s + 1 < M1_NSTEP) cp_wait<1>(); else cp_wait<0>();
        __syncthreads();
        if (s + 1 < M1_NSTEP) ldgB(kb_next);

        const uint32_t* a32 = reinterpret_cast<const uint32_t*>(As) + (s & 1) * (M1_AELEM / 2);
        const uint32_t* bsp = Bs + (s & 1) * M1_BELEM;
#pragma unroll
        for (int kk2 = 0; kk2 < 32; kk2 += 8) {    // 4 x k16 steps
            uint32_t a[4][4];
#pragma unroll
            for (int mi = 0; mi < 4; mi++) {
                int r0 = wm * 64 + mi * 16;
                a[mi][0] = a32[(r0 + gi) * 36 + kk2 + tg];
                a[mi][1] = a32[(r0 + gi + 8) * 36 + kk2 + tg];
                a[mi][2] = a32[(r0 + gi) * 36 + kk2 + tg + 4];
                a[mi][3] = a32[(r0 + gi + 8) * 36 + kk2 + tg + 4];
            }
            uint32_t b[4][2];
#pragma unroll
            for (int ni = 0; ni < 4; ni++) {
                int c0 = wn * 32 + ni * 8;
                b[ni][0] = bsp[(kk2 + tg) * M1_BSTR + c0 + gi];
                b[ni][1] = bsp[(kk2 + tg + 4) * M1_BSTR + c0 + gi];
            }
#pragma unroll
            for (int mi = 0; mi < 4; mi++)
#pragma unroll
                for (int ni = 0; ni < 4; ni++)
                    mma16(acc[mi][ni], a[mi], b[ni][0], b[ni][1]);
        }
        __syncthreads();
    }

    float* Cout = P + (size_t)blockIdx.z * (size_t)BB * (size_t)FD;
#pragma unroll
    for (int mi = 0; mi < 4; mi++) {
#pragma unroll
        for (int ni = 0; ni < 4; ni++) {
            int row = wm * 64 + mi * 16 + gi;
            int col = n0 + wn * 32 + ni * 8 + tg * 2;
            Cout[(size_t)row * FD + col] = acc[mi][ni][0];
            Cout[(size_t)row * FD + col + 1] = acc[mi][ni][1];
            Cout[(size_t)(row + 8) * FD + col] = acc[mi][ni][2];
            Cout[(size_t)(row + 8) * FD + col + 1] = acc[mi][ni][3];
        }
    }
}

// ---------------- split reduce + bias + activation ----------------
__global__ __launch_bounds__(256) void reduce_kernel(
    const float* __restrict__ part, const float* __restrict__ bias,
    float* __restrict__ out, int MN, int N, int splits, int act)
{
    int i = blockIdx.x * 256 + threadIdx.x;
    if (i >= MN) return;
    float s = 0.f;
    for (int z = 0; z < splits; z++) s += part[(size_t)z * MN + i];
    s += bias[i % N];
    if (act) s = 1.f / (1.f + __expf(-s));
    out[i] = s;
}

// ---------------- attention: softmax(K Q^T) V ----------------
// phase1 (K Q^T) in bf16 mma16; softmax fp32; phase3 (S V) in tf32.
// smem: S fp32 [64][260] | kt bf16 u32[64][68] | qv union (q bf16 u32[128][68] /
//       v fp32 [128][132]) | rs [64]
#define ATTN_S_ELEM (64 * 260)
#define ATTN_KT_ELEM (64 * 68)
#define ATTN_QV_ELEM (128 * 132)
#define ATTN_SMEM_BYTES ((ATTN_S_ELEM + ATTN_KT_ELEM + ATTN_QV_ELEM + 64) * 4)

__global__ __launch_bounds__(256) void attn_kernel(
    const float* __restrict__ qkv, __nv_bfloat16* __restrict__ r)
{
    extern __shared__ float sm[];
    float* S = sm;                                          // [64][260]
    uint32_t* kt = reinterpret_cast<uint32_t*>(sm + ATTN_S_ELEM);      // [64][68] bf16x2
    float* qv = sm + ATTN_S_ELEM + ATTN_KT_ELEM;            // phase1: u32[128][68]; phase3: f32[128][132]
    uint32_t* qv32 = reinterpret_cast<uint32_t*>(qv);
    float* rs = qv + ATTN_QV_ELEM;                          // [64]

    const int b = blockIdx.y;
    const int t0 = blockIdx.x * 64;
    const float* qb = qkv + (size_t)b * TT * SQ;
    const float* kb = qkv + ((size_t)b * TT + t0) * SQ + 128;
    const float* vb = qkv + (size_t)b * TT * SQ + 256;
    const int tid = threadIdx.x, warp = tid >> 5, lane = tid & 31;
    const int gi = lane >> 2, tg = lane & 3;
    const int wm = warp & 1, wn = warp >> 1;      // 2(M) x 4(N); warp tile 32x32

    // stage k tile [64][128] as packed bf16
#pragma unroll
    for (int it = 0; it < 8; it++) {
        int idx = tid + it * 256;
        int row = idx >> 5;
        int c4 = (idx & 31) << 2;
        float4 v4 = *reinterpret_cast<const float4*>(kb + (size_t)row * SQ + c4);
        uint2 u;
        u.x = pack_bf2(v4.x, v4.y);
        u.y = pack_bf2(v4.z, v4.w);
        *reinterpret_cast<uint2*>(&kt[row * 68 + (c4 >> 1)]) = u;
    }

    // ---- phase 1: S[t, s] = k . q  (bf16 mma16) ----
    for (int sc = 0; sc < 2; sc++) {
        __syncthreads();
#pragma unroll
        for (int it = 0; it < 16; it++) {
            int idx = tid + it * 256;
            int row = idx >> 5;
            int c4 = (idx & 31) << 2;
            float4 v4 = *reinterpret_cast<const float4*>(qb + (size_t)(sc * 128 + row) * SQ + c4);
            uint2 u;
            u.x = pack_bf2(v4.x, v4.y);
            u.y = pack_bf2(v4.z, v4.w);
            *reinterpret_cast<uint2*>(&qv32[row * 68 + (c4 >> 1)]) = u;
        }
        __syncthreads();
        float acc[2][4][4];
#pragma unroll
        for (int i = 0; i < 2; i++)
#pragma unroll
            for (int j = 0; j < 4; j++)
#pragma unroll
                for (int x = 0; x < 4; x++) acc[i][j][x] = 0.f;
#pragma unroll
        for (int kk2 = 0; kk2 < 64; kk2 += 8) {       // 8 x k16 steps (K=128)
            uint32_t a[2][4];
#pragma unroll
            for (int mi = 0; mi < 2; mi++) {
                int r0 = wm * 32 + mi * 16;
                a[mi][0] = kt[(r0 + gi) * 68 + kk2 + tg];
                a[mi][1] = kt[(r0 + gi + 8) * 68 + kk2 + tg];
                a[mi][2] = kt[(r0 + gi) * 68 + kk2 + tg + 4];
                a[mi][3] = kt[(r0 + gi + 8) * 68 + kk2 + tg + 4];
            }
#pragma unroll
            for (int ni = 0; ni < 4; ni++) {
                int c0 = wn * 32 + ni * 8;
                uint32_t b0 = qv32[(c0 + gi) * 68 + kk2 + tg];
                uint32_t b1 = qv32[(c0 + gi) * 68 + kk2 + tg + 4];
                mma16(acc[0][ni], a[0], b0, b1);
                mma16(acc[1][ni], a[1], b0, b1);
            }
        }
#pragma unroll
        for (int mi = 0; mi < 2; mi++)
#pragma unroll
            for (int ni = 0; ni < 4; ni++) {
                int row = wm * 32 + mi * 16 + gi;
                int col = sc * 128 + wn * 32 + ni * 8 + tg * 2;
                S[row * 260 + col] = acc[mi][ni][0];
                S[row * 260 + col + 1] = acc[mi][ni][1];
                S[(row + 8) * 260 + col] = acc[mi][ni][2];
                S[(row + 8) * 260 + col + 1] = acc[mi][ni][3];
            }
    }
    __syncthreads();

    // ---- phase 2: row softmax; store tf32-rounded exp, keep 1/rowsum ----
#pragma unroll
    for (int rr = 0; rr < 8; rr++) {
        int row = warp * 8 + rr;
        float m = -1e30f;
        for (int j = lane; j < 256; j += 32) m = fmaxf(m, S[row * 260 + j]);
#pragma unroll
        for (int o = 16; o; o >>= 1) m = fmaxf(m, __shfl_xor_sync(0xffffffffu, m, o));
        float sum = 0.f;
        for (int j = lane; j < 256; j += 32) {
            float e = f2tff(__expf(S[row * 260 + j] - m));
            S[row * 260 + j] = e;
            sum += e;
        }
#pragma unroll
        for (int o = 16; o; o >>= 1) sum += __shfl_xor_sync(0xffffffffu, sum, o);
        if (lane == 0) rs[row] = 1.f / sum;
    }
    __syncthreads();

    // ---- phase 3: r = exp(S) @ v (tf32), scaled by 1/rowsum ----
    float acc[2][4][4];
#pragma unroll
    for (int i = 0; i < 2; i++)
#pragma unroll
        for (int j = 0; j < 4; j++)
#pragma unroll
            for (int x = 0; x < 4; x++) acc[i][j][x] = 0.f;

    for (int sc = 0; sc < 2; sc++) {
#pragma unroll
        for (int it = 0; it < 16; it++) {
            int idx = tid + it * 256;
            int row = idx >> 5;
            int c4 = (idx & 31) << 2;
            float4 v4 = *reinterpret_cast<const float4*>(vb + (size_t)(sc * 128 + row) * SQ + c4);
            v4.x = f2tff(v4.x); v4.y = f2tff(v4.y); v4.z = f2tff(v4.z); v4.w = f2tff(v4.w);
            *reinterpret_cast<float4*>(&qv[row * 132 + c4]) = v4;
        }
        __syncthreads();
#pragma unroll
        for (int kk = 0; kk < 128; kk += 8) {
            uint32_t a[2][4];
#pragma unroll
            for (int mi = 0; mi < 2; mi++) {
                int r0 = wm * 32 + mi * 16;
                a[mi][0] = __float_as_uint(S[(r0 + gi) * 260 + sc * 128 + kk + tg]);
                a[mi][1] = __float_as_uint(S[(r0 + gi + 8) * 260 + sc * 128 + kk + tg]);
                a[mi][2] = __float_as_uint(S[(r0 + gi) * 260 + sc * 128 + kk + tg + 4]);
                a[mi][3] = __float_as_uint(S[(r0 + gi + 8) * 260 + sc * 128 + kk + tg + 4]);
            }
#pragma unroll
            for (int ni = 0; ni < 4; ni++) {
                int c0 = wn * 32 + ni * 8;
                uint32_t b0 = __float_as_uint(qv[(kk + tg) * 132 + c0 + gi]);
                uint32_t b1 = __float_as_uint(qv[(kk + tg + 4) * 132 + c0 + gi]);
                mma8(acc[0][ni], a[0], b0, b1);
                mma8(acc[1][ni], a[1], b0, b1);
            }
        }
        __syncthreads();
    }

    __nv_bfloat16* rb = r + ((size_t)b * TT + t0) * VD;
#pragma unroll
    for (int mi = 0; mi < 2; mi++)
#pragma unroll
        for (int ni = 0; ni < 4; ni++) {
            int row = wm * 32 + mi * 16 + gi;
            int col = wn * 32 + ni * 8 + tg * 2;
            float s0 = rs[row], s1 = rs[row + 8];
            rb[(size_t)row * VD + col]     = __float2bfloat16(acc[mi][ni][0] * s0);
            rb[(size_t)row * VD + col + 1] = __float2bfloat16(acc[mi][ni][1] * s0);
            rb[(size_t)(row + 8) * VD + col]     = __float2bfloat16(acc[mi][ni][2] * s1);
            rb[(size_t)(row + 8) * VD + col + 1] = __float2bfloat16(acc[mi][ni][3] * s1);
        }
}

// ---------------- launch ----------------
extern "C" void kernel_launch(void* const* d_in, const int* in_sizes, int n_in,
                              void* d_out, int out_size)
{
    const float* X  = (const float*)d_in[0];
    const float* Qw = (const float*)d_in[1];
    const float* Qb = (const float*)d_in[2];
    const float* Kw = (const float*)d_in[3];
    const float* Kb = (const float*)d_in[4];
    const float* Vw = (const float*)d_in[5];
    const float* Vb = (const float*)d_in[6];
    const float* W1 = (const float*)d_in[7];
    const float* b1 = (const float*)d_in[8];
    const float* W2 = (const float*)d_in[9];
    const float* b2 = (const float*)d_in[10];
    const float* W3 = (const float*)d_in[11];
    const float* b3 = (const float*)d_in[12];
    float* out = (float*)d_out;

    float *qkvp, *wp, *bp, *h1p, *h2p, *pp;
    __nv_bfloat16* rbp;
    cudaGetSymbolAddress((void**)&qkvp, g_qkv);
    cudaGetSymbolAddress((void**)&wp, g_wqkv);
    cudaGetSymbolAddress((void**)&bp, g_bqkv);
    cudaGetSymbolAddress((void**)&rbp, g_rb);
    cudaGetSymbolAddress((void**)&h1p, g_h1);
    cudaGetSymbolAddress((void**)&h2p, g_h2);
    cudaGetSymbolAddress((void**)&pp, g_part);

    cudaFuncSetAttribute(attn_kernel, cudaFuncAttributeMaxDynamicSharedMemorySize,
                         ATTN_SMEM_BYTES);
    cudaFuncSetAttribute(gemm_tf32_pipe, cudaFuncAttributeMaxDynamicSharedMemorySize,
                         GEMM_SMEM);
    cudaFuncSetAttribute(mlp1_bf16_kernel, cudaFuncAttributeMaxDynamicSharedMemorySize,
                         M1_SMEM);

    // pack fused QKV weight + bias
    pack_qkv_kernel<<<(ND * SQ + 255) / 256, 256>>>(Qw, Kw, Vw, Qb, Kb, Vb, wp, bp);

    // fused QKV projection: [32768,128] @ [128,384] + bias, output stride 384
    gemm_tf32_pipe<<<dim3(3, 256, 1), 128, GEMM_SMEM>>>(X, wp, qkvp, bp, BB * TT, SQ, ND, 0);

    // attention (phase1 bf16; writes r as bf16)
    attn_kernel<<<dim3(4, 128), 256, ATTN_SMEM_BYTES>>>(qkvp, rbp);

    // MLP layer 1 (bf16 tensor): [128, 32768] @ [32768, 2048], split-K 32 + sigmoid reduce
    mlp1_bf16_kernel<<<dim3(FD / 64, 1, M1_SPLITS), 128, M1_SMEM>>>(rbp, W1, pp);
    reduce_kernel<<<(BB * FD + 255) / 256, 256>>>(pp, b1, h1p, BB * FD, FD, M1_SPLITS, 1);

    // MLP layer 2: [128, 2048] @ [2048, 2048], split-K 16 + sigmoid reduce
    gemm_tf32_pipe<<<dim3(FD / 128, 1, 16), 128, GEMM_SMEM>>>(h1p, W2, pp, nullptr, BB, FD, FD, 0);
    reduce_kernel<<<(BB * FD + 255) / 256, 256>>>(pp, b2, h2p, BB * FD, FD, 16, 1);

    // MLP layer 3: [128, 2048] @ [2048, 4096], split-K 8 + bias (no act) -> out
    gemm_tf32_pipe<<<dim3(OD / 128, 1, 8), 128, GEMM_SMEM>>>(h2p, W3, pp, nullptr, BB, OD, FD, 0);
    reduce_kernel<<<(BB * OD + 255) / 256, 256>>>(pp, b3, out, BB * OD, OD, 8, 0);
}

// round 10
// speedup vs baseline: 1.3404x; 1.0425x over previous
#include <cuda_runtime.h>
#include <cuda_bf16.h>
#include <cstdint>

// ---------------- problem dims ----------------
#define BB 128
#define TT 256
#define ND 128
#define KD 128
#define VD 128
#define FD 2048
#define OD 4096   // ODIM*NDIM
#define SQ 384    // fused qkv row stride
#define K1 32768  // MLP1 K = TT*VD

// ---------------- device scratch (no allocations allowed) ----------------
__device__ float g_qkv[(size_t)BB * TT * SQ];            // fused q|k|v fp32, stride 384
__device__ float g_wqkv[ND * SQ];                        // packed [128][384] weight fp32
__device__ float g_bqkv[SQ];
__device__ __nv_bfloat16 g_xb[(size_t)BB * TT * ND];     // X as bf16
__device__ __nv_bfloat16 g_rb[(size_t)BB * TT * VD];     // attention out bf16
__device__ __nv_bfloat16 g_h1b[BB * FD];
__device__ float g_h2[BB * FD];                          // fp32! (feeds tf32 MLP3)
__device__ float g_part[(size_t)32 * BB * FD];           // split-K partials

// ---------------- mma helpers ----------------
__device__ __forceinline__ uint32_t f2tf(float f) {
    uint32_t u;
    asm("cvt.rna.tf32.f32 %0, %1;" : "=r"(u) : "f"(f));
    return u;
}

__device__ __forceinline__ void mma8(float* c, const uint32_t* a, uint32_t b0, uint32_t b1) {
    asm volatile(
        "mma.sync.aligned.m16n8k8.row.col.f32.tf32.tf32.f32 "
        "{%0,%1,%2,%3},{%4,%5,%6,%7},{%8,%9},{%0,%1,%2,%3};"
        : "+f"(c[0]), "+f"(c[1]), "+f"(c[2]), "+f"(c[3])
        : "r"(a[0]), "r"(a[1]), "r"(a[2]), "r"(a[3]), "r"(b0), "r"(b1));
}

__device__ __forceinline__ void mma16(float* c, const uint32_t* a, uint32_t b0, uint32_t b1) {
    asm volatile(
        "mma.sync.aligned.m16n8k16.row.col.f32.bf16.bf16.f32 "
        "{%0,%1,%2,%3},{%4,%5,%6,%7},{%8,%9},{%0,%1,%2,%3};"
        : "+f"(c[0]), "+f"(c[1]), "+f"(c[2]), "+f"(c[3])
        : "r"(a[0]), "r"(a[1]), "r"(a[2]), "r"(a[3]), "r"(b0), "r"(b1));
}

__device__ __forceinline__ uint32_t pack_bf2(float lo, float hi) {
    __nv_bfloat162 h = __floats2bfloat162_rn(lo, hi);   // low half = lo (even k)
    return *reinterpret_cast<uint32_t*>(&h);
}

__device__ __forceinline__ void cp16(void* dst, const void* src) {
    uint32_t d = (uint32_t)__cvta_generic_to_shared(dst);
    asm volatile("cp.async.cg.shared.global [%0], [%1], 16;" :: "r"(d), "l"(src));
}
__device__ __forceinline__ void cp_commit() { asm volatile("cp.async.commit_group;"); }
template <int N> __device__ __forceinline__ void cp_wait() {
    asm volatile("cp.async.wait_group %0;" :: "n"(N));
}

// ---------------- small prep kernels ----------------
__global__ void cvt_bf16_kernel(const float* __restrict__ in,
                                __nv_bfloat16* __restrict__ out, int n4)
{
    int i = blockIdx.x * 256 + threadIdx.x;
    if (i < n4) {
        float4 v = reinterpret_cast<const float4*>(in)[i];
        uint2 u;
        u.x = pack_bf2(v.x, v.y);
        u.y = pack_bf2(v.z, v.w);
        reinterpret_cast<uint2*>(out)[i] = u;
    }
}

__global__ void pack_qkv_kernel(
    const float* __restrict__ Qw, const float* __restrict__ Kw, const float* __restrict__ Vw,
    const float* __restrict__ Qb, const float* __restrict__ Kb, const float* __restrict__ Vb,
    float* __restrict__ w, float* __restrict__ bia)
{
    int idx = blockIdx.x * 256 + threadIdx.x;
    if (idx < ND * SQ) {
        int k = idx / SQ, c = idx % SQ;
        float v;
        if (c < 128)       v = Qw[k * 128 + c];
        else if (c < 256)  v = Kw[k * 128 + c - 128];
        else               v = Vw[k * 128 + c - 256];
        w[idx] = v;
    }
    if (idx < SQ) {
        float v;
        if (idx < 128)      v = Qb[idx];
        else if (idx < 256) v = Kb[idx - 128];
        else                v = Vb[idx - 256];
        bia[idx] = v;
    }
}

// ---------------- generic bf16 GEMM (QKV, MLP1, MLP2) ----------------
// C/P = A_bf16[M,K] @ bf16(B_fp32[K,N]).  CTA 128(m) x 64(n), 128 thr,
// 4 warps 2x2 (64x32 each), kstep 64 (4x k16).  A triple-buffered cp.async;
// B via LDG->pack->STS double buffer.
#define GA_ASTR 72                       // bf16 per A row (64+8)
#define GA_BSTR 72                       // u32 per B pair-row (64+8)
#define GA_AELEM (128 * GA_ASTR)         // bf16 per A stage
#define GA_BELEM (32 * GA_BSTR)          // u32 per B stage
#define GA_SMEM (3 * GA_AELEM * 2 + 2 * GA_BELEM * 4)

__global__ __launch_bounds__(128, 3) void gemm_bf16_kernel(
    const __nv_bfloat16* __restrict__ A, const float* __restrict__ Bm,
    float* __restrict__ C, const float* __restrict__ bias,
    int M, int N, int K, int act)
{
    extern __shared__ char smraw[];
    __nv_bfloat16* As = reinterpret_cast<__nv_bfloat16*>(smraw);          // [3][128][72]
    uint32_t* Bs = reinterpret_cast<uint32_t*>(smraw + 3 * GA_AELEM * 2); // [2][32][72]

    const int splits = gridDim.z;
    const int kchunk = K / splits;
    const int kbeg = blockIdx.z * kchunk;
    const int nsteps = kchunk >> 6;
    const int m0 = blockIdx.y * 128;
    const int n0 = blockIdx.x * 64;
    const int tid = threadIdx.x;
    const int warp = tid >> 5, lane = tid & 31;
    const int wm = warp & 1, wn = warp >> 1;
    const int gi = lane >> 2, tg = lane & 3;

    float acc[4][4][4];
#pragma unroll
    for (int i = 0; i < 4; i++)
#pragma unroll
        for (int j = 0; j < 4; j++)
#pragma unroll
            for (int x = 0; x < 4; x++) acc[i][j][x] = 0.f;

    float4 blo[4], bhi[4];

    auto ldgB = [&](int kb) {
#pragma unroll
        for (int j = 0; j < 4; j++) {
            int c = j * 128 + tid;                 // 512 pair-chunks
            int pr = c >> 4;                       // pair-row 0..31
            int colc = (c & 15) << 2;
            const float* p0 = Bm + (size_t)(kb + 2 * pr) * N + n0 + colc;
            blo[j] = *reinterpret_cast<const float4*>(p0);
            bhi[j] = *reinterpret_cast<const float4*>(p0 + N);
        }
    };
    auto stsB = [&](int s) {
        uint32_t* bs = Bs + s * GA_BELEM;
#pragma unroll
        for (int j = 0; j < 4; j++) {
            int c = j * 128 + tid;
            int pr = c >> 4;
            int colc = (c & 15) << 2;
            uint4 u;
            u.x = pack_bf2(blo[j].x, bhi[j].x);
            u.y = pack_bf2(blo[j].y, bhi[j].y);
            u.z = pack_bf2(blo[j].z, bhi[j].z);
            u.w = pack_bf2(blo[j].w, bhi[j].w);
            *reinterpret_cast<uint4*>(&bs[pr * GA_BSTR + colc]) = u;
        }
    };
    auto stageA = [&](int s, int kb) {
        __nv_bfloat16* as = As + s * GA_AELEM;
#pragma unroll
        for (int it = 0; it < 8; it++) {
            int flat = it * 128 + tid;             // 1024 chunks of 16B
            int row = flat >> 3, ch = (flat & 7) << 3;
            cp16(&as[row * GA_ASTR + ch], A + (size_t)(m0 + row) * K + kb + ch);
        }
        cp_commit();
    };

    stageA(0, kbeg);
    ldgB(kbeg);

    for (int s = 0; s < nsteps; s++) {
        const int kb_next = kbeg + (s + 1) * 64;
        if (s + 1 < nsteps) stageA((s + 1) % 3, kb_next);   // triple-buffer: no WAR race
        stsB(s & 1);
        if (s + 1 < nsteps) cp_wait<1>(); else cp_wait<0>();
        __syncthreads();
        if (s + 1 < nsteps) ldgB(kb_next);

        const uint32_t* a32 = reinterpret_cast<const uint32_t*>(As) + (s % 3) * (GA_AELEM / 2);
        const uint32_t* bsp = Bs + (s & 1) * GA_BELEM;
#pragma unroll
        for (int kk2 = 0; kk2 < 32; kk2 += 8) {
            uint32_t a[4][4];
#pragma unroll
            for (int mi = 0; mi < 4; mi++) {
                int r0 = wm * 64 + mi * 16;
                a[mi][0] = a32[(r0 + gi) * 36 + kk2 + tg];
                a[mi][1] = a32[(r0 + gi + 8) * 36 + kk2 + tg];
                a[mi][2] = a32[(r0 + gi) * 36 + kk2 + tg + 4];
                a[mi][3] = a32[(r0 + gi + 8) * 36 + kk2 + tg + 4];
            }
            uint32_t b[4][2];
#pragma unroll
            for (int ni = 0; ni < 4; ni++) {
                int c0 = wn * 32 + ni * 8;
                b[ni][0] = bsp[(kk2 + tg) * GA_BSTR + c0 + gi];
                b[ni][1] = bsp[(kk2 + tg + 4) * GA_BSTR + c0 + gi];
            }
#pragma unroll
            for (int mi = 0; mi < 4; mi++)
#pragma unroll
                for (int ni = 0; ni < 4; ni++)
                    mma16(acc[mi][ni], a[mi], b[ni][0], b[ni][1]);
        }
        __syncthreads();
    }

    if (splits == 1) {
#pragma unroll
        for (int mi = 0; mi < 4; mi++)
#pragma unroll
            for (int ni = 0; ni < 4; ni++) {
                int row = m0 + wm * 64 + mi * 16 + gi;
                int col = n0 + wn * 32 + ni * 8 + tg * 2;
                float bv0 = bias ? bias[col] : 0.f;
                float bv1 = bias ? bias[col + 1] : 0.f;
                float c0 = acc[mi][ni][0] + bv0, c1 = acc[mi][ni][1] + bv1;
                float c2 = acc[mi][ni][2] + bv0, c3 = acc[mi][ni][3] + bv1;
                if (act == 1) {
                    c0 = 1.f / (1.f + __expf(-c0));
                    c1 = 1.f / (1.f + __expf(-c1));
                    c2 = 1.f / (1.f + __expf(-c2));
                    c3 = 1.f / (1.f + __expf(-c3));
                }
                C[(size_t)row * N + col] = c0;
                C[(size_t)row * N + col + 1] = c1;
                C[(size_t)(row + 8) * N + col] = c2;
                C[(size_t)(row + 8) * N + col + 1] = c3;
            }
    } else {
        float* Cout = C + (size_t)blockIdx.z * (size_t)M * (size_t)N;
#pragma unroll
        for (int mi = 0; mi < 4; mi++)
#pragma unroll
            for (int ni = 0; ni < 4; ni++) {
                int row = m0 + wm * 64 + mi * 16 + gi;
                int col = n0 + wn * 32 + ni * 8 + tg * 2;
                Cout[(size_t)row * N + col] = acc[mi][ni][0];
                Cout[(size_t)row * N + col + 1] = acc[mi][ni][1];
                Cout[(size_t)(row + 8) * N + col] = acc[mi][ni][2];
                Cout[(size_t)(row + 8) * N + col + 1] = acc[mi][ni][3];
            }
    }
}

// ---------------- tf32 GEMM (MLP3 only — precision-critical final layer) ----------------
#define ASTRIDE 36
#define BSTRIDE 136
#define GEMM_SMEM ((2 * 128 * ASTRIDE + 2 * 32 * BSTRIDE) * 4)

__global__ __launch_bounds__(128, 2) void gemm_tf32_pipe(
    const float* __restrict__ A, const float* __restrict__ Bm,
    float* __restrict__ C, int M, int N, int K)
{
    extern __shared__ float smp[];
    float* As = smp;                          // [2][128][ASTRIDE]
    float* Bs = smp + 2 * 128 * ASTRIDE;      // [2][32][BSTRIDE]

    const int splits = gridDim.z;
    const int kchunk = K / splits;
    const int kbeg = blockIdx.z * kchunk;
    const int m0 = blockIdx.y * 128;
    const int n0 = blockIdx.x * 128;
    const int tid = threadIdx.x;
    const int warp = tid >> 5, lane = tid & 31;
    const int wm = warp & 1, wn = warp >> 1;      // 2x2; warp tile 64x64
    const int gi = lane >> 2, tg = lane & 3;

    float acc[4][8][4];
#pragma unroll
    for (int i = 0; i < 4; i++)
#pragma unroll
        for (int j = 0; j < 8; j++)
#pragma unroll
            for (int x = 0; x < 4; x++) acc[i][j][x] = 0.f;

    auto stage = [&](int s, int kb) {
        float* as = As + s * (128 * ASTRIDE);
        float* bs = Bs + s * (32 * BSTRIDE);
#pragma unroll
        for (int it = 0; it < 8; it++) {
            int flat = it * 128 + tid;
            int row = flat >> 3, c4 = (flat & 7) << 2;
            cp16(&as[row * ASTRIDE + c4], A + (size_t)(m0 + row) * K + kb + c4);
        }
#pragma unroll
        for (int it = 0; it < 8; it++) {
            int flat = it * 128 + tid;
            int row = flat >> 5, c4 = (flat & 31) << 2;
            cp16(&bs[row * BSTRIDE + c4], Bm + (size_t)(kb + row) * N + n0 + c4);
        }
        cp_commit();
    };

    const int nsteps = kchunk / 32;
    stage(0, kbeg);

    for (int s = 0; s < nsteps; s++) {
        if (s + 1 < nsteps) { stage((s + 1) & 1, kbeg + (s + 1) * 32); cp_wait<1>(); }
        else cp_wait<0>();
        __syncthreads();
        float* as = As + (s & 1) * (128 * ASTRIDE);
        float* bs = Bs + (s & 1) * (32 * BSTRIDE);
#pragma unroll
        for (int kk = 0; kk < 32; kk += 8) {
            uint32_t a[4][4];
#pragma unroll
            for (int mi = 0; mi < 4; mi++) {
                int r0 = wm * 64 + mi * 16;
                a[mi][0] = f2tf(as[(r0 + gi) * ASTRIDE + kk + tg]);
                a[mi][1] = f2tf(as[(r0 + gi + 8) * ASTRIDE + kk + tg]);
                a[mi][2] = f2tf(as[(r0 + gi) * ASTRIDE + kk + tg + 4]);
                a[mi][3] = f2tf(as[(r0 + gi + 8) * ASTRIDE + kk + tg + 4]);
            }
            uint32_t b[8][2];
#pragma unroll
            for (int ni = 0; ni < 8; ni++) {
                int c0 = wn * 64 + ni * 8;
                b[ni][0] = f2tf(bs[(kk + tg) * BSTRIDE + c0 + gi]);
                b[ni][1] = f2tf(bs[(kk + tg + 4) * BSTRIDE + c0 + gi]);
            }
#pragma unroll
            for (int mi = 0; mi < 4; mi++)
#pragma unroll
                for (int ni = 0; ni < 8; ni++)
                    mma8(acc[mi][ni], a[mi], b[ni][0], b[ni][1]);
        }
        __syncthreads();
    }

    float* Cout = C + (size_t)blockIdx.z * (size_t)M * (size_t)N;
#pragma unroll
    for (int mi = 0; mi < 4; mi++)
#pragma unroll
        for (int ni = 0; ni < 8; ni++) {
            int row = m0 + wm * 64 + mi * 16 + gi;
            int col = n0 + wn * 64 + ni * 8 + tg * 2;
            Cout[(size_t)row * N + col] = acc[mi][ni][0];
            Cout[(size_t)row * N + col + 1] = acc[mi][ni][1];
            Cout[(size_t)(row + 8) * N + col] = acc[mi][ni][2];
            Cout[(size_t)(row + 8) * N + col + 1] = acc[mi][ni][3];
        }
}

// ---------------- split reduces ----------------
__global__ __launch_bounds__(256) void reduce_f32_kernel(
    const float* __restrict__ part, const float* __restrict__ bias,
    float* __restrict__ out, int MN, int N, int splits, int act)
{
    int i = blockIdx.x * 256 + threadIdx.x;
    if (i >= MN) return;
    float s = 0.f;
    for (int z = 0; z < splits; z++) s += part[(size_t)z * MN + i];
    s += bias[i % N];
    if (act) s = 1.f / (1.f + __expf(-s));
    out[i] = s;
}

__global__ __launch_bounds__(256) void reduce_bf16_kernel(
    const float* __restrict__ part, const float* __restrict__ bias,
    __nv_bfloat16* __restrict__ out, int MN, int N, int splits)
{
    int i = blockIdx.x * 256 + threadIdx.x;
    if (i >= MN) return;
    float s = 0.f;
    for (int z = 0; z < splits; z++) s += part[(size_t)z * MN + i];
    s += bias[i % N];
    s = 1.f / (1.f + __expf(-s));
    out[i] = __float2bfloat16(s);
}

// ---------------- attention: softmax(K Q^T) V, all-bf16 mma ----------------
#define AT_S 0
#define AT_KT (64 * 260)
#define AT_QV (AT_KT + 64 * 68)
#define AT_SB (AT_QV + 128 * 132)
#define AT_RS (AT_SB + 64 * 132)
#define ATTN_SMEM_BYTES ((AT_RS + 64) * 4)

__global__ __launch_bounds__(256) void attn_kernel(
    const float* __restrict__ qkv, __nv_bfloat16* __restrict__ r)
{
    extern __shared__ float sm[];
    float* S = sm + AT_S;                                        // [64][260]
    uint32_t* kt = reinterpret_cast<uint32_t*>(sm + AT_KT);      // [64][68] bf16x2 (k pairs)
    float* qv = sm + AT_QV;
    uint32_t* qv32 = reinterpret_cast<uint32_t*>(qv);            // q: [128][68] / v: [64][136]
    uint32_t* Sb = reinterpret_cast<uint32_t*>(sm + AT_SB);      // [64][132] bf16x2 (s pairs)
    float* rs = sm + AT_RS;                                      // [64]

    const int b = blockIdx.y;
    const int t0 = blockIdx.x * 64;
    const float* qb = qkv + (size_t)b * TT * SQ;
    const float* kb = qkv + ((size_t)b * TT + t0) * SQ + 128;
    const float* vb = qkv + (size_t)b * TT * SQ + 256;
    const int tid = threadIdx.x, warp = tid >> 5, lane = tid & 31;
    const int gi = lane >> 2, tg = lane & 3;
    const int wm = warp & 1, wn = warp >> 1;      // 2(M) x 4(N); warp tile 32x32

#pragma unroll
    for (int it = 0; it < 8; it++) {
        int idx = tid + it * 256;
        int row = idx >> 5;
        int c4 = (idx & 31) << 2;
        float4 v4 = *reinterpret_cast<const float4*>(kb + (size_t)row * SQ + c4);
        uint2 u;
        u.x = pack_bf2(v4.x, v4.y);
        u.y = pack_bf2(v4.z, v4.w);
        *reinterpret_cast<uint2*>(&kt[row * 68 + (c4 >> 1)]) = u;
    }

    // ---- phase 1: S = k . q (bf16) ----
    for (int sc = 0; sc < 2; sc++) {
        __syncthreads();
#pragma unroll
        for (int it = 0; it < 16; it++) {
            int idx = tid + it * 256;
            int row = idx >> 5;
            int c4 = (idx & 31) << 2;
            float4 v4 = *reinterpret_cast<const float4*>(qb + (size_t)(sc * 128 + row) * SQ + c4);
            uint2 u;
            u.x = pack_bf2(v4.x, v4.y);
            u.y = pack_bf2(v4.z, v4.w);
            *reinterpret_cast<uint2*>(&qv32[row * 68 + (c4 >> 1)]) = u;
        }
        __syncthreads();
        float acc[2][4][4];
#pragma unroll
        for (int i = 0; i < 2; i++)
#pragma unroll
            for (int j = 0; j < 4; j++)
#pragma unroll
                for (int x = 0; x < 4; x++) acc[i][j][x] = 0.f;
#pragma unroll
        for (int kk2 = 0; kk2 < 64; kk2 += 8) {
            uint32_t a[2][4];
#pragma unroll
            for (int mi = 0; mi < 2; mi++) {
                int r0 = wm * 32 + mi * 16;
                a[mi][0] = kt[(r0 + gi) * 68 + kk2 + tg];
                a[mi][1] = kt[(r0 + gi + 8) * 68 + kk2 + tg];
                a[mi][2] = kt[(r0 + gi) * 68 + kk2 + tg + 4];
                a[mi][3] = kt[(r0 + gi + 8) * 68 + kk2 + tg + 4];
            }
#pragma unroll
            for (int ni = 0; ni < 4; ni++) {
                int c0 = wn * 32 + ni * 8;
                uint32_t b0 = qv32[(c0 + gi) * 68 + kk2 + tg];
                uint32_t b1 = qv32[(c0 + gi) * 68 + kk2 + tg + 4];
                mma16(acc[0][ni], a[0], b0, b1);
                mma16(acc[1][ni], a[1], b0, b1);
            }
        }
#pragma unroll
        for (int mi = 0; mi < 2; mi++)
#pragma unroll
            for (int ni = 0; ni < 4; ni++) {
                int row = wm * 32 + mi * 16 + gi;
                int col = sc * 128 + wn * 32 + ni * 8 + tg * 2;
                S[row * 260 + col] = acc[mi][ni][0];
                S[row * 260 + col + 1] = acc[mi][ni][1];
                S[(row + 8) * 260 + col] = acc[mi][ni][2];
                S[(row + 8) * 260 + col + 1] = acc[mi][ni][3];
            }
    }
    __syncthreads();

    // ---- phase 2: row softmax ----
#pragma unroll
    for (int rr = 0; rr < 8; rr++) {
        int row = warp * 8 + rr;
        float m = -1e30f;
        for (int j = lane; j < 256; j += 32) m = fmaxf(m, S[row * 260 + j]);
#pragma unroll
        for (int o = 16; o; o >>= 1) m = fmaxf(m, __shfl_xor_sync(0xffffffffu, m, o));
        float sum = 0.f;
        for (int j = lane; j < 256; j += 32) {
            float e = __expf(S[row * 260 + j] - m);
            S[row * 260 + j] = e;
            sum += e;
        }
#pragma unroll
        for (int o = 16; o; o >>= 1) sum += __shfl_xor_sync(0xffffffffu, sum, o);
        if (lane == 0) rs[row] = 1.f / sum;
    }
    __syncthreads();

    // ---- repack exp(S) -> bf16 s-pairs ----
#pragma unroll
    for (int it = 0; it < 32; it++) {
        int idx = tid + it * 256;
        int row = idx >> 7;
        int p = idx & 127;
        float2 e = *reinterpret_cast<const float2*>(&S[row * 260 + 2 * p]);
        Sb[row * 132 + p] = pack_bf2(e.x, e.y);
    }

    // ---- phase 3: r = exp(S) @ v (bf16) ----
    float acc[2][4][4];
#pragma unroll
    for (int i = 0; i < 2; i++)
#pragma unroll
        for (int j = 0; j < 4; j++)
#pragma unroll
            for (int x = 0; x < 4; x++) acc[i][j][x] = 0.f;

    for (int sc = 0; sc < 2; sc++) {
        __syncthreads();
#pragma unroll
        for (int it = 0; it < 8; it++) {
            int c = tid + it * 256;
            int pr = c >> 5;
            int c4 = (c & 31) << 2;
            const float* p0 = vb + (size_t)(sc * 128 + 2 * pr) * SQ + c4;
            float4 lo = *reinterpret_cast<const float4*>(p0);
            float4 hi = *reinterpret_cast<const float4*>(p0 + SQ);
            uint4 u;
            u.x = pack_bf2(lo.x, hi.x);
            u.y = pack_bf2(lo.y, hi.y);
            u.z = pack_bf2(lo.z, hi.z);
            u.w = pack_bf2(lo.w, hi.w);
            *reinterpret_cast<uint4*>(&qv32[pr * 136 + c4]) = u;
        }
        __syncthreads();
#pragma unroll
        for (int kk2 = 0; kk2 < 64; kk2 += 8) {
            uint32_t a[2][4];
#pragma unroll
            for (int mi = 0; mi < 2; mi++) {
                int r0 = wm * 32 + mi * 16;
                a[mi][0] = Sb[(r0 + gi) * 132 + sc * 64 + kk2 + tg];
                a[mi][1] = Sb[(r0 + gi + 8) * 132 + sc * 64 + kk2 + tg];
                a[mi][2] = Sb[(r0 + gi) * 132 + sc * 64 + kk2 + tg + 4];
                a[mi][3] = Sb[(r0 + gi + 8) * 132 + sc * 64 + kk2 + tg + 4];
            }
#pragma unroll
            for (int ni = 0; ni < 4; ni++) {
                int c0 = wn * 32 + ni * 8;
                uint32_t b0 = qv32[(kk2 + tg) * 136 + c0 + gi];
                uint32_t b1 = qv32[(kk2 + tg + 4) * 136 + c0 + gi];
                mma16(acc[0][ni], a[0], b0, b1);
                mma16(acc[1][ni], a[1], b0, b1);
            }
        }
    }

    __nv_bfloat16* rb = r + ((size_t)b * TT + t0) * VD;
#pragma unroll
    for (int mi = 0; mi < 2; mi++)
#pragma unroll
        for (int ni = 0; ni < 4; ni++) {
            int row = wm * 32 + mi * 16 + gi;
            int col = wn * 32 + ni * 8 + tg * 2;
            float s0 = rs[row], s1 = rs[row + 8];
            rb[(size_t)row * VD + col]     = __float2bfloat16(acc[mi][ni][0] * s0);
            rb[(size_t)row * VD + col + 1] = __float2bfloat16(acc[mi][ni][1] * s0);
            rb[(size_t)(row + 8) * VD + col]     = __float2bfloat16(acc[mi][ni][2] * s1);
            rb[(size_t)(row + 8) * VD + col + 1] = __float2bfloat16(acc[mi][ni][3] * s1);
        }
}

// ---------------- launch ----------------
extern "C" void kernel_launch(void* const* d_in, const int* in_sizes, int n_in,
                              void* d_out, int out_size)
{
    const float* X  = (const float*)d_in[0];
    const float* Qw = (const float*)d_in[1];
    const float* Qb = (const float*)d_in[2];
    const float* Kw = (const float*)d_in[3];
    const float* Kb = (const float*)d_in[4];
    const float* Vw = (const float*)d_in[5];
    const float* Vb = (const float*)d_in[6];
    const float* W1 = (const float*)d_in[7];
    const float* b1 = (const float*)d_in[8];
    const float* W2 = (const float*)d_in[9];
    const float* b2 = (const float*)d_in[10];
    const float* W3 = (const float*)d_in[11];
    const float* b3 = (const float*)d_in[12];
    float* out = (float*)d_out;

    float *qkvp, *wp, *bp, *h2p, *pp;
    __nv_bfloat16 *xbp, *rbp, *h1bp;
    cudaGetSymbolAddress((void**)&qkvp, g_qkv);
    cudaGetSymbolAddress((void**)&wp, g_wqkv);
    cudaGetSymbolAddress((void**)&bp, g_bqkv);
    cudaGetSymbolAddress((void**)&xbp, g_xb);
    cudaGetSymbolAddress((void**)&rbp, g_rb);
    cudaGetSymbolAddress((void**)&h1bp, g_h1b);
    cudaGetSymbolAddress((void**)&h2p, g_h2);
    cudaGetSymbolAddress((void**)&pp, g_part);

    cudaFuncSetAttribute(attn_kernel, cudaFuncAttributeMaxDynamicSharedMemorySize,
                         ATTN_SMEM_BYTES);
    cudaFuncSetAttribute(gemm_bf16_kernel, cudaFuncAttributeMaxDynamicSharedMemorySize,
                         GA_SMEM);
    cudaFuncSetAttribute(gemm_tf32_pipe, cudaFuncAttributeMaxDynamicSharedMemorySize,
                         GEMM_SMEM);

    // X -> bf16 ; pack fused QKV weight + bias
    cvt_bf16_kernel<<<(BB * TT * ND / 4 + 255) / 256, 256>>>(X, xbp, BB * TT * ND / 4);
    pack_qkv_kernel<<<(ND * SQ + 255) / 256, 256>>>(Qw, Kw, Vw, Qb, Kb, Vb, wp, bp);

    // fused QKV projection (bf16): [32768,128] @ [128,384] + bias -> fp32 qkv
    gemm_bf16_kernel<<<dim3(SQ / 64, 256, 1), 128, GA_SMEM>>>(
        xbp, wp, qkvp, bp, BB * TT, SQ, ND, 0);

    // attention (bf16 mma, writes bf16 r)
    attn_kernel<<<dim3(4, 128), 256, ATTN_SMEM_BYTES>>>(qkvp, rbp);

    // MLP1 (bf16): [128,32768]@[32768,2048] split 32 -> sigmoid bf16 h1
    gemm_bf16_kernel<<<dim3(FD / 64, 1, 32), 128, GA_SMEM>>>(
        rbp, W1, pp, nullptr, BB, FD, K1, 0);
    reduce_bf16_kernel<<<(BB * FD + 255) / 256, 256>>>(pp, b1, h1bp, BB * FD, FD, 32);

    // MLP2 (bf16): [128,2048]@[2048,2048] split 16 -> sigmoid fp32 h2
    gemm_bf16_kernel<<<dim3(FD / 64, 1, 16), 128, GA_SMEM>>>(
        h1bp, W2, pp, nullptr, BB, FD, FD, 0);
    reduce_f32_kernel<<<(BB * FD + 255) / 256, 256>>>(pp, b2, h2p, BB * FD, FD, 16, 1);

    // MLP3 (tf32 — precision-critical): [128,2048]@[2048,4096] split 8 + bias -> fp32 out
    gemm_tf32_pipe<<<dim3(OD / 128, 1, 8), 128, GEMM_SMEM>>>(h2p, W3, pp, BB, OD, FD);
    reduce_f32_kernel<<<(BB * OD + 255) / 256, 256>>>(pp, b3, out, BB * OD, OD, 8, 0);
}

// round 13
// speedup vs baseline: 1.5647x; 1.1673x over previous
#include <cuda_runtime.h>
#include <cuda_bf16.h>
#include <cstdint>

// ---------------- problem dims ----------------
#define BB 128
#define TT 256
#define ND 128
#define KD 128
#define VD 128
#define FD 2048
#define OD 4096   // ODIM*NDIM
#define SQ 384    // fused qkv row stride
#define K1 32768  // MLP1 K = TT*VD

// ---------------- device scratch (no allocations allowed) ----------------
__device__ __nv_bfloat16 g_qkv[(size_t)BB * TT * SQ];    // fused q|k|v bf16, stride 384
__device__ float g_wqkv[ND * SQ];                        // packed [128][384] weight fp32
__device__ float g_bqkv[SQ];
__device__ __nv_bfloat16 g_xb[(size_t)BB * TT * ND];     // X as bf16
__device__ __nv_bfloat16 g_rb[(size_t)BB * TT * VD];     // attention out bf16
__device__ __nv_bfloat16 g_h1b[BB * FD];
__device__ float g_h2[BB * FD];                          // fp32 (feeds tf32 MLP3)
__device__ float g_part[(size_t)32 * BB * FD];           // split-K partials

// ---------------- mma helpers ----------------
__device__ __forceinline__ uint32_t f2tf(float f) {
    uint32_t u;
    asm("cvt.rna.tf32.f32 %0, %1;" : "=r"(u) : "f"(f));
    return u;
}

__device__ __forceinline__ void mma8(float* c, const uint32_t* a, uint32_t b0, uint32_t b1) {
    asm volatile(
        "mma.sync.aligned.m16n8k8.row.col.f32.tf32.tf32.f32 "
        "{%0,%1,%2,%3},{%4,%5,%6,%7},{%8,%9},{%0,%1,%2,%3};"
        : "+f"(c[0]), "+f"(c[1]), "+f"(c[2]), "+f"(c[3])
        : "r"(a[0]), "r"(a[1]), "r"(a[2]), "r"(a[3]), "r"(b0), "r"(b1));
}

__device__ __forceinline__ void mma16(float* c, const uint32_t* a, uint32_t b0, uint32_t b1) {
    asm volatile(
        "mma.sync.aligned.m16n8k16.row.col.f32.bf16.bf16.f32 "
        "{%0,%1,%2,%3},{%4,%5,%6,%7},{%8,%9},{%0,%1,%2,%3};"
        : "+f"(c[0]), "+f"(c[1]), "+f"(c[2]), "+f"(c[3])
        : "r"(a[0]), "r"(a[1]), "r"(a[2]), "r"(a[3]), "r"(b0), "r"(b1));
}

__device__ __forceinline__ uint32_t pack_bf2(float lo, float hi) {
    __nv_bfloat162 h = __floats2bfloat162_rn(lo, hi);   // low half = lo (even k)
    return *reinterpret_cast<uint32_t*>(&h);
}

__device__ __forceinline__ void cp16(void* dst, const void* src) {
    uint32_t d = (uint32_t)__cvta_generic_to_shared(dst);
    asm volatile("cp.async.cg.shared.global [%0], [%1], 16;" :: "r"(d), "l"(src));
}
__device__ __forceinline__ void cp_commit() { asm volatile("cp.async.commit_group;"); }
template <int N> __device__ __forceinline__ void cp_wait() {
    asm volatile("cp.async.wait_group %0;" :: "n"(N));
}

// ---------------- small prep kernels ----------------
__global__ void cvt_bf16_kernel(const float* __restrict__ in,
                                __nv_bfloat16* __restrict__ out, int n4)
{
    int i = blockIdx.x * 256 + threadIdx.x;
    if (i < n4) {
        float4 v = reinterpret_cast<const float4*>(in)[i];
        uint2 u;
        u.x = pack_bf2(v.x, v.y);
        u.y = pack_bf2(v.z, v.w);
        reinterpret_cast<uint2*>(out)[i] = u;
    }
}

__global__ void pack_qkv_kernel(
    const float* __restrict__ Qw, const float* __restrict__ Kw, const float* __restrict__ Vw,
    const float* __restrict__ Qb, const float* __restrict__ Kb, const float* __restrict__ Vb,
    float* __restrict__ w, float* __restrict__ bia)
{
    int idx = blockIdx.x * 256 + threadIdx.x;
    if (idx < ND * SQ) {
        int k = idx / SQ, c = idx % SQ;
        float v;
        if (c < 128)       v = Qw[k * 128 + c];
        else if (c < 256)  v = Kw[k * 128 + c - 128];
        else               v = Vw[k * 128 + c - 256];
        w[idx] = v;
    }
    if (idx < SQ) {
        float v;
        if (idx < 128)      v = Qb[idx];
        else if (idx < 256) v = Kb[idx - 128];
        else                v = Vb[idx - 256];
        bia[idx] = v;
    }
}

// ---------------- generic bf16 GEMM (QKV, MLP1, MLP2) ----------------
// C/P = A_bf16[M,K] @ bf16(B_fp32[K,N]).  CTA 128(m) x 64(n), 128 thr,
// 4 warps 2x2 (64x32 each), kstep 64 (4x k16).  A triple-buffered cp.async;
// B via LDG->pack->STS double buffer.
// act: 0 = f32 bias store, 1 = f32 sigmoid, 2 = bf16 bias store (splits==1 only)
#define GA_ASTR 72                       // bf16 per A row (64+8)
#define GA_BSTR 72                       // u32 per B pair-row (64+8)
#define GA_AELEM (128 * GA_ASTR)         // bf16 per A stage
#define GA_BELEM (32 * GA_BSTR)          // u32 per B stage
#define GA_SMEM (3 * GA_AELEM * 2 + 2 * GA_BELEM * 4)

__global__ __launch_bounds__(128, 3) void gemm_bf16_kernel(
    const __nv_bfloat16* __restrict__ A, const float* __restrict__ Bm,
    void* __restrict__ Cv, const float* __restrict__ bias,
    int M, int N, int K, int act)
{
    extern __shared__ char smraw[];
    __nv_bfloat16* As = reinterpret_cast<__nv_bfloat16*>(smraw);          // [3][128][72]
    uint32_t* Bs = reinterpret_cast<uint32_t*>(smraw + 3 * GA_AELEM * 2); // [2][32][72]

    const int splits = gridDim.z;
    const int kchunk = K / splits;
    const int kbeg = blockIdx.z * kchunk;
    const int nsteps = kchunk >> 6;
    const int m0 = blockIdx.y * 128;
    const int n0 = blockIdx.x * 64;
    const int tid = threadIdx.x;
    const int warp = tid >> 5, lane = tid & 31;
    const int wm = warp & 1, wn = warp >> 1;
    const int gi = lane >> 2, tg = lane & 3;

    float acc[4][4][4];
#pragma unroll
    for (int i = 0; i < 4; i++)
#pragma unroll
        for (int j = 0; j < 4; j++)
#pragma unroll
            for (int x = 0; x < 4; x++) acc[i][j][x] = 0.f;

    float4 blo[4], bhi[4];

    auto ldgB = [&](int kb) {
#pragma unroll
        for (int j = 0; j < 4; j++) {
            int c = j * 128 + tid;                 // 512 pair-chunks
            int pr = c >> 4;                       // pair-row 0..31
            int colc = (c & 15) << 2;
            const float* p0 = Bm + (size_t)(kb + 2 * pr) * N + n0 + colc;
            blo[j] = *reinterpret_cast<const float4*>(p0);
            bhi[j] = *reinterpret_cast<const float4*>(p0 + N);
        }
    };
    auto stsB = [&](int s) {
        uint32_t* bs = Bs + s * GA_BELEM;
#pragma unroll
        for (int j = 0; j < 4; j++) {
            int c = j * 128 + tid;
            int pr = c >> 4;
            int colc = (c & 15) << 2;
            uint4 u;
            u.x = pack_bf2(blo[j].x, bhi[j].x);
            u.y = pack_bf2(blo[j].y, bhi[j].y);
            u.z = pack_bf2(blo[j].z, bhi[j].z);
            u.w = pack_bf2(blo[j].w, bhi[j].w);
            *reinterpret_cast<uint4*>(&bs[pr * GA_BSTR + colc]) = u;
        }
    };
    auto stageA = [&](int s, int kb) {
        __nv_bfloat16* as = As + s * GA_AELEM;
#pragma unroll
        for (int it = 0; it < 8; it++) {
            int flat = it * 128 + tid;             // 1024 chunks of 16B
            int row = flat >> 3, ch = (flat & 7) << 3;
            cp16(&as[row * GA_ASTR + ch], A + (size_t)(m0 + row) * K + kb + ch);
        }
        cp_commit();
    };

    stageA(0, kbeg);
    ldgB(kbeg);

    for (int s = 0; s < nsteps; s++) {
        const int kb_next = kbeg + (s + 1) * 64;
        if (s + 1 < nsteps) stageA((s + 1) % 3, kb_next);
        stsB(s & 1);
        if (s + 1 < nsteps) cp_wait<1>(); else cp_wait<0>();
        __syncthreads();
        if (s + 1 < nsteps) ldgB(kb_next);

        const uint32_t* a32 = reinterpret_cast<const uint32_t*>(As) + (s % 3) * (GA_AELEM / 2);
        const uint32_t* bsp = Bs + (s & 1) * GA_BELEM;
#pragma unroll
        for (int kk2 = 0; kk2 < 32; kk2 += 8) {
            uint32_t a[4][4];
#pragma unroll
            for (int mi = 0; mi < 4; mi++) {
                int r0 = wm * 64 + mi * 16;
                a[mi][0] = a32[(r0 + gi) * 36 + kk2 + tg];
                a[mi][1] = a32[(r0 + gi + 8) * 36 + kk2 + tg];
                a[mi][2] = a32[(r0 + gi) * 36 + kk2 + tg + 4];
                a[mi][3] = a32[(r0 + gi + 8) * 36 + kk2 + tg + 4];
            }
            uint32_t b[4][2];
#pragma unroll
            for (int ni = 0; ni < 4; ni++) {
                int c0 = wn * 32 + ni * 8;
                b[ni][0] = bsp[(kk2 + tg) * GA_BSTR + c0 + gi];
                b[ni][1] = bsp[(kk2 + tg + 4) * GA_BSTR + c0 + gi];
            }
#pragma unroll
            for (int mi = 0; mi < 4; mi++)
#pragma unroll
                for (int ni = 0; ni < 4; ni++)
                    mma16(acc[mi][ni], a[mi], b[ni][0], b[ni][1]);
        }
        __syncthreads();
    }

    if (splits == 1) {
#pragma unroll
        for (int mi = 0; mi < 4; mi++)
#pragma unroll
            for (int ni = 0; ni < 4; ni++) {
                int row = m0 + wm * 64 + mi * 16 + gi;
                int col = n0 + wn * 32 + ni * 8 + tg * 2;
                float bv0 = bias ? bias[col] : 0.f;
                float bv1 = bias ? bias[col + 1] : 0.f;
                float c0 = acc[mi][ni][0] + bv0, c1 = acc[mi][ni][1] + bv1;
                float c2 = acc[mi][ni][2] + bv0, c3 = acc[mi][ni][3] + bv1;
                if (act == 1) {
                    c0 = 1.f / (1.f + __expf(-c0));
                    c1 = 1.f / (1.f + __expf(-c1));
                    c2 = 1.f / (1.f + __expf(-c2));
                    c3 = 1.f / (1.f + __expf(-c3));
                }
                if (act == 2) {
                    __nv_bfloat16* Cb = (__nv_bfloat16*)Cv;
                    *reinterpret_cast<uint32_t*>(&Cb[(size_t)row * N + col]) = pack_bf2(c0, c1);
                    *reinterpret_cast<uint32_t*>(&Cb[(size_t)(row + 8) * N + col]) = pack_bf2(c2, c3);
                } else {
                    float* C = (float*)Cv;
                    C[(size_t)row * N + col] = c0;
                    C[(size_t)row * N + col + 1] = c1;
                    C[(size_t)(row + 8) * N + col] = c2;
                    C[(size_t)(row + 8) * N + col + 1] = c3;
                }
            }
    } else {
        float* Cout = (float*)Cv + (size_t)blockIdx.z * (size_t)M * (size_t)N;
#pragma unroll
        for (int mi = 0; mi < 4; mi++)
#pragma unroll
            for (int ni = 0; ni < 4; ni++) {
                int row = m0 + wm * 64 + mi * 16 + gi;
                int col = n0 + wn * 32 + ni * 8 + tg * 2;
                Cout[(size_t)row * N + col] = acc[mi][ni][0];
                Cout[(size_t)row * N + col + 1] = acc[mi][ni][1];
                Cout[(size_t)(row + 8) * N + col] = acc[mi][ni][2];
                Cout[(size_t)(row + 8) * N + col + 1] = acc[mi][ni][3];
            }
    }
}

// ---------------- tf32 GEMM (MLP3 only — precision-critical final layer) ----------------
#define ASTRIDE 36
#define BSTRIDE 136
#define GEMM_SMEM ((2 * 128 * ASTRIDE + 2 * 32 * BSTRIDE) * 4)

__global__ __launch_bounds__(128, 2) void gemm_tf32_pipe(
    const float* __restrict__ A, const float* __restrict__ Bm,
    float* __restrict__ C, int M, int N, int K)
{
    extern __shared__ float smp[];
    float* As = smp;
    float* Bs = smp + 2 * 128 * ASTRIDE;

    const int splits = gridDim.z;
    const int kchunk = K / splits;
    const int kbeg = blockIdx.z * kchunk;
    const int m0 = blockIdx.y * 128;
    const int n0 = blockIdx.x * 128;
    const int tid = threadIdx.x;
    const int warp = tid >> 5, lane = tid & 31;
    const int wm = warp & 1, wn = warp >> 1;
    const int gi = lane >> 2, tg = lane & 3;

    float acc[4][8][4];
#pragma unroll
    for (int i = 0; i < 4; i++)
#pragma unroll
        for (int j = 0; j < 8; j++)
#pragma unroll
            for (int x = 0; x < 4; x++) acc[i][j][x] = 0.f;

    auto stage = [&](int s, int kb) {
        float* as = As + s * (128 * ASTRIDE);
        float* bs = Bs + s * (32 * BSTRIDE);
#pragma unroll
        for (int it = 0; it < 8; it++) {
            int flat = it * 128 + tid;
            int row = flat >> 3, c4 = (flat & 7) << 2;
            cp16(&as[row * ASTRIDE + c4], A + (size_t)(m0 + row) * K + kb + c4);
        }
#pragma unroll
        for (int it = 0; it < 8; it++) {
            int flat = it * 128 + tid;
            int row = flat >> 5, c4 = (flat & 31) << 2;
            cp16(&bs[row * BSTRIDE + c4], Bm + (size_t)(kb + row) * N + n0 + c4);
        }
        cp_commit();
    };

    const int nsteps = kchunk / 32;
    stage(0, kbeg);

    for (int s = 0; s < nsteps; s++) {
        if (s + 1 < nsteps) { stage((s + 1) & 1, kbeg + (s + 1) * 32); cp_wait<1>(); }
        else cp_wait<0>();
        __syncthreads();
        float* as = As + (s & 1) * (128 * ASTRIDE);
        float* bs = Bs + (s & 1) * (32 * BSTRIDE);
#pragma unroll
        for (int kk = 0; kk < 32; kk += 8) {
            uint32_t a[4][4];
#pragma unroll
            for (int mi = 0; mi < 4; mi++) {
                int r0 = wm * 64 + mi * 16;
                a[mi][0] = f2tf(as[(r0 + gi) * ASTRIDE + kk + tg]);
                a[mi][1] = f2tf(as[(r0 + gi + 8) * ASTRIDE + kk + tg]);
                a[mi][2] = f2tf(as[(r0 + gi) * ASTRIDE + kk + tg + 4]);
                a[mi][3] = f2tf(as[(r0 + gi + 8) * ASTRIDE + kk + tg + 4]);
            }
            uint32_t b[8][2];
#pragma unroll
            for (int ni = 0; ni < 8; ni++) {
                int c0 = wn * 64 + ni * 8;
                b[ni][0] = f2tf(bs[(kk + tg) * BSTRIDE + c0 + gi]);
                b[ni][1] = f2tf(bs[(kk + tg + 4) * BSTRIDE + c0 + gi]);
            }
#pragma unroll
            for (int mi = 0; mi < 4; mi++)
#pragma unroll
                for (int ni = 0; ni < 8; ni++)
                    mma8(acc[mi][ni], a[mi], b[ni][0], b[ni][1]);
        }
        __syncthreads();
    }

    float* Cout = C + (size_t)blockIdx.z * (size_t)M * (size_t)N;
#pragma unroll
    for (int mi = 0; mi < 4; mi++)
#pragma unroll
        for (int ni = 0; ni < 8; ni++) {
            int row = m0 + wm * 64 + mi * 16 + gi;
            int col = n0 + wn * 64 + ni * 8 + tg * 2;
            Cout[(size_t)row * N + col] = acc[mi][ni][0];
            Cout[(size_t)row * N + col + 1] = acc[mi][ni][1];
            Cout[(size_t)(row + 8) * N + col] = acc[mi][ni][2];
            Cout[(size_t)(row + 8) * N + col + 1] = acc[mi][ni][3];
        }
}

// ---------------- split reduces ----------------
__global__ __launch_bounds__(256) void reduce_f32_kernel(
    const float* __restrict__ part, const float* __restrict__ bias,
    float* __restrict__ out, int MN, int N, int splits, int act)
{
    int i = blockIdx.x * 256 + threadIdx.x;
    if (i >= MN) return;
    float s = 0.f;
    for (int z = 0; z < splits; z++) s += part[(size_t)z * MN + i];
    s += bias[i % N];
    if (act) s = 1.f / (1.f + __expf(-s));
    out[i] = s;
}

__global__ __launch_bounds__(256) void reduce_bf16_kernel(
    const float* __restrict__ part, const float* __restrict__ bias,
    __nv_bfloat16* __restrict__ out, int MN, int N, int splits)
{
    int i = blockIdx.x * 256 + threadIdx.x;
    if (i >= MN) return;
    float s = 0.f;
    for (int z = 0; z < splits; z++) s += part[(size_t)z * MN + i];
    s += bias[i % N];
    s = 1.f / (1.f + __expf(-s));
    out[i] = __float2bfloat16(s);
}

// ---------------- attention: softmax(K Q^T) V, bf16 qkv, 2 CTAs/SM ----------------
// smem (floats): S fp32 [64][264] | rs[64] | u32 region (phase1: kt[64][68] +
// q[64][68]; phase3: v-pairs [64][136] aliasing both). Total ~102.7 KB.
#define AS_STR 264
#define AT_RS (64 * AS_STR)
#define AT_KQ (AT_RS + 64)
#define ATTN_SMEM_BYTES ((AT_KQ + 8704) * 4)

__global__ __launch_bounds__(256) void attn_kernel(
    const __nv_bfloat16* __restrict__ qkv, __nv_bfloat16* __restrict__ r)
{
    extern __shared__ float sm[];
    float* S = sm;                                           // [64][264]
    float* rs = sm + AT_RS;                                  // [64]
    uint32_t* kq = reinterpret_cast<uint32_t*>(sm + AT_KQ);
    uint32_t* kt = kq;                                       // [64][68] (phase1)
    uint32_t* qs = kq + 64 * 68;                             // [64][68] (phase1)
    uint32_t* vs = kq;                                       // [64][136] (phase3)

    const int b = blockIdx.y;
    const int t0 = blockIdx.x * 64;
    const __nv_bfloat16* qb = qkv + (size_t)b * TT * SQ;
    const __nv_bfloat16* kb = qb + (size_t)t0 * SQ + 128;
    const __nv_bfloat16* vb = qb + 256;
    const int tid = threadIdx.x, warp = tid >> 5, lane = tid & 31;
    const int gi = lane >> 2, tg = lane & 3;
    const int wm = warp & 1, wn = warp >> 1;      // 2(M) x 4(N)

    // stage k tile [64][128] bf16 -> u32 pairs along feature dim (native layout)
#pragma unroll
    for (int it = 0; it < 4; it++) {
        int flat = it * 256 + tid;          // 1024 uint4 chunks
        int row = flat >> 4, q4 = flat & 15;
        *reinterpret_cast<uint4*>(&kt[row * 68 + q4 * 4]) =
            *reinterpret_cast<const uint4*>(kb + (size_t)row * SQ + q4 * 8);
    }

    // ---- phase 1: S[t, s] = k . q (bf16), q staged in 64-row chunks ----
    for (int qc = 0; qc < 4; qc++) {
        __syncthreads();
#pragma unroll
        for (int it = 0; it < 4; it++) {
            int flat = it * 256 + tid;
            int row = flat >> 4, q4 = flat & 15;
            *reinterpret_cast<uint4*>(&qs[row * 68 + q4 * 4]) =
                *reinterpret_cast<const uint4*>(qb + (size_t)(qc * 64 + row) * SQ + q4 * 8);
        }
        __syncthreads();
        float acc[2][2][4];
#pragma unroll
        for (int i = 0; i < 2; i++)
#pragma unroll
            for (int j = 0; j < 2; j++)
#pragma unroll
                for (int x = 0; x < 4; x++) acc[i][j][x] = 0.f;
#pragma unroll
        for (int kk2 = 0; kk2 < 64; kk2 += 8) {
            uint32_t a[2][4];
#pragma unroll
            for (int mi = 0; mi < 2; mi++) {
                int r0 = wm * 32 + mi * 16;
                a[mi][0] = kt[(r0 + gi) * 68 + kk2 + tg];
                a[mi][1] = kt[(r0 + gi + 8) * 68 + kk2 + tg];
                a[mi][2] = kt[(r0 + gi) * 68 + kk2 + tg + 4];
                a[mi][3] = kt[(r0 + gi + 8) * 68 + kk2 + tg + 4];
            }
#pragma unroll
            for (int ni = 0; ni < 2; ni++) {
                int c0 = wn * 16 + ni * 8;
                uint32_t b0 = qs[(c0 + gi) * 68 + kk2 + tg];
                uint32_t b1 = qs[(c0 + gi) * 68 + kk2 + tg + 4];
                mma16(acc[0][ni], a[0], b0, b1);
                mma16(acc[1][ni], a[1], b0, b1);
            }
        }
#pragma unroll
        for (int mi = 0; mi < 2; mi++)
#pragma unroll
            for (int ni = 0; ni < 2; ni++) {
                int row = wm * 32 + mi * 16 + gi;
                int col = qc * 64 + wn * 16 + ni * 8 + tg * 2;
                S[row * AS_STR + col] = acc[mi][ni][0];
                S[row * AS_STR + col + 1] = acc[mi][ni][1];
                S[(row + 8) * AS_STR + col] = acc[mi][ni][2];
                S[(row + 8) * AS_STR + col + 1] = acc[mi][ni][3];
            }
    }
    __syncthreads();

    // ---- phase 2: row softmax (exp stays fp32 in S; 1/rowsum in rs) ----
#pragma unroll
    for (int rr = 0; rr < 8; rr++) {
        int row = warp * 8 + rr;
        float m = -1e30f;
        for (int j = lane; j < 256; j += 32) m = fmaxf(m, S[row * AS_STR + j]);
#pragma unroll
        for (int o = 16; o; o >>= 1) m = fmaxf(m, __shfl_xor_sync(0xffffffffu, m, o));
        float sum = 0.f;
        for (int j = lane; j < 256; j += 32) {
            float e = __expf(S[row * AS_STR + j] - m);
            S[row * AS_STR + j] = e;
            sum += e;
        }
#pragma unroll
        for (int o = 16; o; o >>= 1) sum += __shfl_xor_sync(0xffffffffu, sum, o);
        if (lane == 0) rs[row] = 1.f / sum;
    }
    __syncthreads();

    // ---- phase 3: r = exp(S) @ v (bf16); A frags packed on the fly from fp32 S ----
    float acc[2][4][4];
#pragma unroll
    for (int i = 0; i < 2; i++)
#pragma unroll
        for (int j = 0; j < 4; j++)
#pragma unroll
            for (int x = 0; x < 4; x++) acc[i][j][x] = 0.f;

    for (int sc = 0; sc < 2; sc++) {
        if (sc) __syncthreads();   // all warps done reading vs chunk 0
        // stage v rows [sc*128, +128) as s-dim bf16 pairs: vs[pr][col]
#pragma unroll
        for (int it = 0; it < 4; it++) {
            int flat = it * 256 + tid;      // 1024 chunks: 64 pr x 16 col8
            int pr = flat >> 4, c8 = flat & 15;
            const __nv_bfloat16* p0 = vb + (size_t)(sc * 128 + 2 * pr) * SQ + c8 * 8;
            uint4 lo = *reinterpret_cast<const uint4*>(p0);
            uint4 hi = *reinterpret_cast<const uint4*>(p0 + SQ);
            uint4 o0, o1;
            o0.x = __byte_perm(lo.x, hi.x, 0x5410);
            o0.y = __byte_perm(lo.x, hi.x, 0x7632);
            o0.z = __byte_perm(lo.y, hi.y, 0x5410);
            o0.w = __byte_perm(lo.y, hi.y, 0x7632);
            o1.x = __byte_perm(lo.z, hi.z, 0x5410);
            o1.y = __byte_perm(lo.z, hi.z, 0x7632);
            o1.z = __byte_perm(lo.w, hi.w, 0x5410);
            o1.w = __byte_perm(lo.w, hi.w, 0x7632);
            *reinterpret_cast<uint4*>(&vs[pr * 136 + c8 * 8]) = o0;
            *reinterpret_cast<uint4*>(&vs[pr * 136 + c8 * 8 + 4]) = o1;
        }
        __syncthreads();
#pragma unroll
        for (int kk2 = 0; kk2 < 64; kk2 += 8) {
            uint32_t a[2][4];
#pragma unroll
            for (int mi = 0; mi < 2; mi++) {
                int r0 = wm * 32 + mi * 16;
                float2 e0 = *reinterpret_cast<const float2*>(
                    &S[(r0 + gi) * AS_STR + sc * 128 + 2 * (kk2 + tg)]);
                float2 e1 = *reinterpret_cast<const float2*>(
                    &S[(r0 + gi + 8) * AS_STR + sc * 128 + 2 * (kk2 + tg)]);
                float2 e2 = *reinterpret_cast<const float2*>(
                    &S[(r0 + gi) * AS_STR + sc * 128 + 2 * (kk2 + tg + 4)]);
                float2 e3 = *reinterpret_cast<const float2*>(
                    &S[(r0 + gi + 8) * AS_STR + sc * 128 + 2 * (kk2 + tg + 4)]);
                a[mi][0] = pack_bf2(e0.x, e0.y);
                a[mi][1] = pack_bf2(e1.x, e1.y);
                a[mi][2] = pack_bf2(e2.x, e2.y);
                a[mi][3] = pack_bf2(e3.x, e3.y);
            }
#pragma unroll
            for (int ni = 0; ni < 4; ni++) {
                int c0 = wn * 32 + ni * 8;
                uint32_t b0 = vs[(kk2 + tg) * 136 + c0 + gi];
                uint32_t b1 = vs[(kk2 + tg + 4) * 136 + c0 + gi];
                mma16(acc[0][ni], a[0], b0, b1);
                mma16(acc[1][ni], a[1], b0, b1);
            }
        }
    }

    __nv_bfloat16* rb = r + ((size_t)b * TT + t0) * VD;
#pragma unroll
    for (int mi = 0; mi < 2; mi++)
#pragma unroll
        for (int ni = 0; ni < 4; ni++) {
            int row = wm * 32 + mi * 16 + gi;
            int col = wn * 32 + ni * 8 + tg * 2;
            float s0 = rs[row], s1 = rs[row + 8];
            *reinterpret_cast<uint32_t*>(&rb[(size_t)row * VD + col]) =
                pack_bf2(acc[mi][ni][0] * s0, acc[mi][ni][1] * s0);
            *reinterpret_cast<uint32_t*>(&rb[(size_t)(row + 8) * VD + col]) =
                pack_bf2(acc[mi][ni][2] * s1, acc[mi][ni][3] * s1);
        }
}

// ---------------- launch ----------------
extern "C" void kernel_launch(void* const* d_in, const int* in_sizes, int n_in,
                              void* d_out, int out_size)
{
    const float* X  = (const float*)d_in[0];
    const float* Qw = (const float*)d_in[1];
    const float* Qb = (const float*)d_in[2];
    const float* Kw = (const float*)d_in[3];
    const float* Kb = (const float*)d_in[4];
    const float* Vw = (const float*)d_in[5];
    const float* Vb = (const float*)d_in[6];
    const float* W1 = (const float*)d_in[7];
    const float* b1 = (const float*)d_in[8];
    const float* W2 = (const float*)d_in[9];
    const float* b2 = (const float*)d_in[10];
    const float* W3 = (const float*)d_in[11];
    const float* b3 = (const float*)d_in[12];
    float* out = (float*)d_out;

    float *wp, *bp, *h2p, *pp;
    __nv_bfloat16 *qkvp, *xbp, *rbp, *h1bp;
    cudaGetSymbolAddress((void**)&qkvp, g_qkv);
    cudaGetSymbolAddress((void**)&wp, g_wqkv);
    cudaGetSymbolAddress((void**)&bp, g_bqkv);
    cudaGetSymbolAddress((void**)&xbp, g_xb);
    cudaGetSymbolAddress((void**)&rbp, g_rb);
    cudaGetSymbolAddress((void**)&h1bp, g_h1b);
    cudaGetSymbolAddress((void**)&h2p, g_h2);
    cudaGetSymbolAddress((void**)&pp, g_part);

    cudaFuncSetAttribute(attn_kernel, cudaFuncAttributeMaxDynamicSharedMemorySize,
                         ATTN_SMEM_BYTES);
    cudaFuncSetAttribute(gemm_bf16_kernel, cudaFuncAttributeMaxDynamicSharedMemorySize,
                         GA_SMEM);
    cudaFuncSetAttribute(gemm_tf32_pipe, cudaFuncAttributeMaxDynamicSharedMemorySize,
                         GEMM_SMEM);

    // X -> bf16 ; pack fused QKV weight + bias
    cvt_bf16_kernel<<<(BB * TT * ND / 4 + 255) / 256, 256>>>(X, xbp, BB * TT * ND / 4);
    pack_qkv_kernel<<<(ND * SQ + 255) / 256, 256>>>(Qw, Kw, Vw, Qb, Kb, Vb, wp, bp);

    // fused QKV projection (bf16): [32768,128] @ [128,384] + bias -> bf16 qkv
    gemm_bf16_kernel<<<dim3(SQ / 64, 256, 1), 128, GA_SMEM>>>(
        xbp, wp, qkvp, bp, BB * TT, SQ, ND, 2);

    // attention (bf16 mma, bf16 in/out, 2 CTAs/SM)
    attn_kernel<<<dim3(4, 128), 256, ATTN_SMEM_BYTES>>>(qkvp, rbp);

    // MLP1 (bf16): [128,32768]@[32768,2048] split 32 -> sigmoid bf16 h1
    gemm_bf16_kernel<<<dim3(FD / 64, 1, 32), 128, GA_SMEM>>>(
        rbp, W1, pp, nullptr, BB, FD, K1, 0);
    reduce_bf16_kernel<<<(BB * FD + 255) / 256, 256>>>(pp, b1, h1bp, BB * FD, FD, 32);

    // MLP2 (bf16): [128,2048]@[2048,2048] split 16 -> sigmoid fp32 h2
    gemm_bf16_kernel<<<dim3(FD / 64, 1, 16), 128, GA_SMEM>>>(
        h1bp, W2, pp, nullptr, BB, FD, FD, 0);
    reduce_f32_kernel<<<(BB * FD + 255) / 256, 256>>>(pp, b2, h2p, BB * FD, FD, 16, 1);

    // MLP3 (tf32 — precision-critical): [128,2048]@[2048,4096] split 8 + bias -> fp32 out
    gemm_tf32_pipe<<<dim3(OD / 128, 1, 8), 128, GEMM_SMEM>>>(h2p, W3, pp, BB, OD, FD);
    reduce_f32_kernel<<<(BB * OD + 255) / 256, 256>>>(pp, b3, out, BB * OD, OD, 8, 0);
}